// round 5
// baseline (speedup 1.0000x reference)
#include <cuda_runtime.h>
#include <cuda_bf16.h>
#include <cstdint>

// ---------------------------------------------------------------------------
// RPN: 1x1 conv GEMM -> softmax/decode/clip -> top-12000 select+sort -> greedy NMS
// Outputs: rpn_locs[8,36864,4] | rpn_scores[8,36864,2] | rois[8,600,4] | anchor[1,36864,4]
// Score GEMM accumulation = splitK2 (bit-matches reference); loc GEMM = plain chain.
// ---------------------------------------------------------------------------

#define NB        8
#define NA        36864
#define HW        4096
#define K_DIM     512
#define N_PRE     12000
#define N_POST    600
#define SORT_N    16384

#define OFF_SCORES 1179648
#define OFF_ROIS   1769472
#define OFF_ANCH   1788672

__device__ float4             g_boxes[NB][NA];
__device__ unsigned           g_su[NB][NA];
__device__ unsigned long long g_cand[NB][SORT_N];
__device__ int                g_C[NB];
__device__ int                g_vcnt[NB];
__device__ float4             g_sboxes[NB][N_PRE];

__constant__ float c_aw[9] = {181.01933598375618f, 362.03867196751236f, 724.0773439350247f,
                              128.0f, 256.0f, 512.0f,
                              90.50966799187809f, 181.01933598375618f, 362.03867196751236f};
__constant__ float c_ah[9] = {90.50966799187809f, 181.01933598375618f, 362.03867196751236f,
                              128.0f, 256.0f, 512.0f,
                              181.01933598375618f, 362.03867196751236f, 724.0773439350247f};

// ---------------------------------------------------------------------------
// K1: fused GEMM (UNCHANGED — bit-exact accumulation orders)
// ---------------------------------------------------------------------------
__global__ __launch_bounds__(128) void gemm_kernel(
    const float* __restrict__ x,
    const float* __restrict__ wsc, const float* __restrict__ bsc,
    const float* __restrict__ wlc, const float* __restrict__ blc,
    float* __restrict__ out)
{
    __shared__ float xs[64 * 128];
    __shared__ float ws[54 * 64];
    const int t   = threadIdx.x;
    const int b   = blockIdx.x;
    const int n   = b >> 5;
    const int hw0 = (b & 31) * 128;
    const float* xb = x + n * (K_DIM * HW) + hw0;

    float acc[36];
    float p0[18], p1[18];
#pragma unroll
    for (int o = 0; o < 36; o++) acc[o] = 0.0f;
#pragma unroll
    for (int o = 0; o < 18; o++) { p0[o] = 0.0f; p1[o] = 0.0f; }

    for (int k0 = 0; k0 < K_DIM; k0 += 64) {
#pragma unroll
        for (int it = 0; it < 16; it++) {
            int v = t + it * 128;
            int r = v >> 5;
            int c = v & 31;
            float4 val = *(const float4*)(xb + (k0 + r) * HW + c * 4);
            *(float4*)&xs[r * 128 + c * 4] = val;
        }
        for (int v = t; v < 864; v += 128) {
            int o = v >> 4;
            int c = v & 15;
            const float* row = (o < 36) ? (wlc + o * K_DIM) : (wsc + (o - 36) * K_DIM);
            *(float4*)&ws[o * 64 + c * 4] = *(const float4*)(row + k0 + c * 4);
        }
        __syncthreads();

        float* sc = (k0 < 256) ? p0 : p1;
        for (int kk = 0; kk < 64; kk += 4) {
            float x0 = xs[(kk + 0) * 128 + t];
            float x1 = xs[(kk + 1) * 128 + t];
            float x2 = xs[(kk + 2) * 128 + t];
            float x3 = xs[(kk + 3) * 128 + t];
#pragma unroll
            for (int o = 0; o < 36; o++) {
                float4 w4 = *(float4*)&ws[o * 64 + kk];
                acc[o] = fmaf(x0, w4.x, acc[o]);
                acc[o] = fmaf(x1, w4.y, acc[o]);
                acc[o] = fmaf(x2, w4.z, acc[o]);
                acc[o] = fmaf(x3, w4.w, acc[o]);
            }
#pragma unroll
            for (int o = 0; o < 18; o++) {
                float4 w4 = *(float4*)&ws[(36 + o) * 64 + kk];
                sc[o] = fmaf(x0, w4.x, sc[o]);
                sc[o] = fmaf(x1, w4.y, sc[o]);
                sc[o] = fmaf(x2, w4.z, sc[o]);
                sc[o] = fmaf(x3, w4.w, sc[o]);
            }
        }
        __syncthreads();
    }

    const int hw = hw0 + t;
    float* lout = out + n * (NA * 4) + hw * 36;
#pragma unroll
    for (int o = 0; o < 36; o++) lout[o] = acc[o] + blc[o];
    float* sout = out + OFF_SCORES + n * (NA * 2) + hw * 18;
#pragma unroll
    for (int o = 0; o < 18; o++) sout[o] = (p0[o] + p1[o]) + bsc[o];
}

// ---------------------------------------------------------------------------
// K2: decode (unchanged)
// ---------------------------------------------------------------------------
__global__ void decode_kernel(float* __restrict__ out)
{
    int g = blockIdx.x * blockDim.x + threadIdx.x;
    if (g >= NB * NA) return;
    int n = g / NA;
    int i = g - n * NA;
    int hw = i / 9;
    int a  = i - hw * 9;

    float sx = (float)((hw & 63) * 16);
    float sy = (float)((hw >> 6) * 16);
    float aw = c_aw[a], ah = c_ah[a];
    float ax1 = sx - 0.5f * aw, ay1 = sy - 0.5f * ah;
    float ax2 = sx + 0.5f * aw, ay2 = sy + 0.5f * ah;

    if (n == 0) {
        *(float4*)(out + OFF_ANCH + i * 4) = make_float4(ax1, ay1, ax2, ay2);
    }

    float aww = ax2 - ax1, ahh = ay2 - ay1;
    float acx = ax1 + 0.5f * aww, acy = ay1 + 0.5f * ahh;

    float4 l = *(const float4*)(out + n * (NA * 4) + i * 4);
    float cx = l.x * aww + acx;
    float cy = l.y * ahh + acy;
    float w  = expf(l.z) * aww;
    float h  = expf(l.w) * ahh;

    float x1 = fminf(fmaxf(cx - 0.5f * w, 0.0f), 1024.0f);
    float y1 = fminf(fmaxf(cy - 0.5f * h, 0.0f), 1024.0f);
    float x2 = fminf(fmaxf(cx + 0.5f * w, 0.0f), 1024.0f);
    float y2 = fminf(fmaxf(cy + 0.5f * h, 0.0f), 1024.0f);

    bool valid = ((x2 - x1) >= 16.0f) && ((y2 - y1) >= 16.0f);

    float2 s = *(const float2*)(out + OFF_SCORES + n * (NA * 2) + i * 2);
    float m  = fmaxf(s.x, s.y);
    float e0 = expf(s.x - m), e1 = expf(s.y - m);
    float fg = e1 / (e0 + e1);

    g_su[n][i]    = valid ? (__float_as_uint(fg) | 0x80000000u) : 0u;
    g_boxes[n][i] = make_float4(x1, y1, x2, y2);
}

// ---------------------------------------------------------------------------
// K3: radix select (unchanged)
// ---------------------------------------------------------------------------
__global__ __launch_bounds__(1024) void select_kernel()
{
    __shared__ unsigned hist[4096];
    __shared__ unsigned psum[256];
    __shared__ int sB1, sAbove, sThr, sCnt;

    const int n = blockIdx.x;
    const int t = threadIdx.x;

    for (int v = t; v < 4096; v += 1024) hist[v] = 0;
    __syncthreads();
    for (int i = t; i < NA; i += 1024) {
        unsigned u = g_su[n][i];
        if (u) atomicAdd(&hist[u >> 20], 1u);
    }
    __syncthreads();
    if (t < 256) {
        unsigned s = 0;
#pragma unroll
        for (int j = 0; j < 16; j++) s += hist[t * 16 + j];
        psum[t] = s;
    }
    __syncthreads();
    if (t == 0) {
        unsigned total = 0;
        for (int c = 0; c < 256; c++) total += psum[c];
        if (total <= N_PRE) {
            sThr = 1;
            sB1  = -1;
            g_vcnt[n] = (int)total;
        } else {
            g_vcnt[n] = N_PRE;
            unsigned acc = 0; int c = 255;
            while (acc + psum[c] < N_PRE) { acc += psum[c]; c--; }
            int bkt = c * 16 + 15;
            while (acc + hist[bkt] < N_PRE) { acc += hist[bkt]; bkt--; }
            sB1 = bkt; sAbove = (int)acc; sThr = 0;
        }
    }
    __syncthreads();
    const int B1 = sB1;
    if (sThr == 0) {
        for (int v = t; v < 4096; v += 1024) hist[v] = 0;
        __syncthreads();
        for (int i = t; i < NA; i += 1024) {
            unsigned u = g_su[n][i];
            if (u && (int)(u >> 20) == B1) atomicAdd(&hist[(u >> 8) & 0xFFFu], 1u);
        }
        __syncthreads();
        if (t < 256) {
            unsigned s = 0;
#pragma unroll
            for (int j = 0; j < 16; j++) s += hist[t * 16 + j];
            psum[t] = s;
        }
        __syncthreads();
        if (t == 0) {
            unsigned K2 = (unsigned)(N_PRE - sAbove);
            unsigned acc = 0; int c = 255;
            while (acc + psum[c] < K2) { acc += psum[c]; c--; }
            int bkt = c * 16 + 15;
            while (acc + hist[bkt] < K2) { acc += hist[bkt]; bkt--; }
            sThr = (B1 << 12) | bkt;
        }
    }
    __syncthreads();
    const unsigned thr = (unsigned)sThr;
    if (t == 0) sCnt = 0;
    __syncthreads();
    for (int i = t; i < NA; i += 1024) {
        unsigned u = g_su[n][i];
        if (u && (u >> 8) >= thr) {
            int p = atomicAdd(&sCnt, 1);
            if (p < SORT_N)
                g_cand[n][p] = (((unsigned long long)u) << 32) | (unsigned)(~i);
        }
    }
    __syncthreads();
    if (t == 0) g_C[n] = min(sCnt, SORT_N);
}

// ---------------------------------------------------------------------------
// K4: bitonic sort with register-local sub-networks.
// Each thread owns 16 contiguous keys; all j<=8 phases run in registers.
// smem padded: phys(i) = i + (i>>4)  (kills chunk bank conflicts).
// ---------------------------------------------------------------------------
#define PH(i) ((i) + ((i) >> 4))
#define SORT_SMEM ((SORT_N + SORT_N / 16) * 8)

__device__ __forceinline__ void cswap_desc(unsigned long long& a, unsigned long long& b, bool desc)
{
    // desc: want a >= b ; asc: want a <= b
    bool sw = desc ? (a < b) : (a > b);
    if (sw) { unsigned long long tmp = a; a = b; b = tmp; }
}

__device__ __forceinline__ void merge16(unsigned long long v[16], bool desc)
{
#pragma unroll
    for (int jj = 8; jj >= 1; jj >>= 1)
#pragma unroll
        for (int idx = 0; idx < 16; idx++)
            if ((idx & jj) == 0) cswap_desc(v[idx], v[idx | jj], desc);
}

__global__ __launch_bounds__(1024) void sort_kernel()
{
    extern __shared__ unsigned long long keys[];   // padded: 17408 u64 = 139,264 B
    const int n = blockIdx.x;
    const int t = threadIdx.x;
    const int C = g_C[n];
    const int base = t * 16;

    // load own chunk straight from gmem, fully sort 16 locally (k=2..16 phases)
    unsigned long long v[16];
#pragma unroll
    for (int s = 0; s < 16; s++) {
        int i = base + s;
        v[s] = (i < C) ? g_cand[n][i] : 0ull;
    }
#pragma unroll
    for (int kk = 2; kk <= 8; kk <<= 1)
#pragma unroll
        for (int jj = kk >> 1; jj >= 1; jj >>= 1)
#pragma unroll
            for (int idx = 0; idx < 16; idx++)
                if ((idx & jj) == 0) cswap_desc(v[idx], v[idx | jj], (idx & kk) == 0);
    merge16(v, (t & 1) == 0);          // k=16 phase: dir from (base & 16)
#pragma unroll
    for (int s = 0; s < 16; s++) keys[PH(base + s)] = v[s];
    __syncthreads();

    for (int k = 32; k <= SORT_N; k <<= 1) {
        for (int j = k >> 1; j >= 16; j >>= 1) {
#pragma unroll
            for (int p = 0; p < 16; p++) {
                int i = t + p * 1024;
                int l = i ^ j;
                if (l > i) {
                    unsigned long long a = keys[PH(i)], b = keys[PH(l)];
                    bool desc = ((i & k) == 0);
                    if (desc ? (a < b) : (a > b)) { keys[PH(i)] = b; keys[PH(l)] = a; }
                }
            }
            __syncthreads();
        }
        // local j=8..1 finishing merge (direction constant within 16-chunk)
#pragma unroll
        for (int s = 0; s < 16; s++) v[s] = keys[PH(base + s)];
        merge16(v, (base & k) == 0);
#pragma unroll
        for (int s = 0; s < 16; s++) keys[PH(base + s)] = v[s];
        __syncthreads();
    }

    for (int p = t; p < N_PRE; p += 1024) {
        unsigned long long kk = keys[PH(p)];
        unsigned idx = ~(unsigned)(kk & 0xFFFFFFFFull);
        float4 b = (kk != 0ull) ? g_boxes[n][idx] : make_float4(0.f, 0.f, 0.f, 0.f);
        g_sboxes[n][p] = b;
    }
}

// ---------------------------------------------------------------------------
// K5: greedy NMS. 512 threads, 24 boxes/thread. Boxes in SMEM (192KB),
// areas in registers. ONE barrier per accept via double-buffered warp minima.
// ---------------------------------------------------------------------------
#define NMS_T     512
#define BOX_PER_T 24
#define NMS_SMEM  (N_PRE * 16)

__global__ __launch_bounds__(NMS_T) void nms_kernel(float* __restrict__ out)
{
    extern __shared__ float4 s_boxes[];          // [N_PRE]
    __shared__ int warpmin[2][16];
    __shared__ int s_keep[N_POST];

    const int n = blockIdx.x;
    const int t = threadIdx.x;
    const int wid = t >> 5;
    const int vcnt = g_vcnt[n];
    const int base = t * BOX_PER_T;

    for (int i = t; i < N_PRE; i += NMS_T)
        s_boxes[i] = g_sboxes[n][i];
    __syncthreads();

    float ar[BOX_PER_T];
    unsigned live = 0;
#pragma unroll
    for (int s = 0; s < BOX_PER_T; s++) {
        int i = base + s;
        if (i < N_PRE) {
            float4 b = s_boxes[i];
            ar[s] = fmaxf(b.z - b.x, 0.f) * fmaxf(b.w - b.y, 0.f);
            if (i < vcnt) live |= 1u << s;
        } else {
            ar[s] = 0.f;
        }
    }

    // initial per-warp min
    {
        int lm = live ? (base + __ffs(live) - 1) : 0x7FFFFFFF;
        lm = __reduce_min_sync(0xFFFFFFFFu, lm);
        if ((t & 31) == 0) warpmin[0][wid] = lm;
    }
    __syncthreads();

    int kept = 0;
    for (int it = 0; it < N_POST; it++) {
        const int p = it & 1;
        int nxt = warpmin[p][0];
#pragma unroll
        for (int w = 1; w < 16; w++) nxt = min(nxt, warpmin[p][w]);
        if (nxt == 0x7FFFFFFF) break;
        if (t == 0) s_keep[it] = nxt;
        kept = it + 1;

        float4 cb = s_boxes[nxt];                    // smem broadcast
        float ca = fmaxf(cb.z - cb.x, 0.f) * fmaxf(cb.w - cb.y, 0.f);
        int rel = nxt - base;
        if (rel >= 0 && rel < BOX_PER_T) live &= ~(1u << rel);

        if (live) {
            float lo = 0.69f * ca;
            float hi = 0.69f;  // used as: ca < 0.69*a1
#pragma unroll
            for (int s = 0; s < BOX_PER_T; s++) {
                if (live & (1u << s)) {
                    float a1 = ar[s];
                    if (a1 < lo || ca < hi * a1) continue;   // conservative area prune
                    float4 b = s_boxes[base + s];
                    float iw = fminf(b.z, cb.z) - fmaxf(b.x, cb.x);
                    if (iw <= 0.f) continue;
                    float ih = fminf(b.w, cb.w) - fmaxf(b.y, cb.y);
                    if (ih <= 0.f) continue;
                    float inter = iw * ih;
                    float iou = inter / (ca + a1 - inter + 1e-9f);  // exact reference form
                    if (iou > 0.7f)
                        live &= ~(1u << s);
                }
            }
        }

        int lm = live ? (base + __ffs(live) - 1) : 0x7FFFFFFF;
        lm = __reduce_min_sync(0xFFFFFFFFu, lm);
        if ((t & 31) == 0) warpmin[p ^ 1][wid] = lm;
        __syncthreads();
    }

    __syncthreads();
    for (int e = t; e < N_POST; e += NMS_T) {
        int ki = (e < kept) ? s_keep[e] : (e - kept);   // pad like the reference
        float4 b = s_boxes[ki];
        *(float4*)(out + OFF_ROIS + n * (N_POST * 4) + e * 4) = b;
    }
}

// ---------------------------------------------------------------------------
extern "C" void kernel_launch(void* const* d_in, const int* in_sizes, int n_in,
                              void* d_out, int out_size)
{
    const float* x   = (const float*)d_in[0];
    const float* wsc = (const float*)d_in[1];
    const float* bsc = (const float*)d_in[2];
    const float* wlc = (const float*)d_in[3];
    const float* blc = (const float*)d_in[4];
    float* out = (float*)d_out;

    cudaFuncSetAttribute(sort_kernel, cudaFuncAttributeMaxDynamicSharedMemorySize, SORT_SMEM);
    cudaFuncSetAttribute(nms_kernel,  cudaFuncAttributeMaxDynamicSharedMemorySize, NMS_SMEM);

    gemm_kernel<<<256, 128>>>(x, wsc, bsc, wlc, blc, out);
    decode_kernel<<<(NB * NA + 255) / 256, 256>>>(out);
    select_kernel<<<NB, 1024>>>();
    sort_kernel<<<NB, 1024, SORT_SMEM>>>();
    nms_kernel<<<NB, NMS_T, NMS_SMEM>>>(out);
}

// round 6
// speedup vs baseline: 1.2983x; 1.2983x over previous
#include <cuda_runtime.h>
#include <cuda_bf16.h>
#include <cstdint>

// ---------------------------------------------------------------------------
// RPN: 1x1 conv GEMM -> softmax/decode/clip -> top-12000 select+sort -> greedy NMS
// Outputs: rpn_locs[8,36864,4] | rpn_scores[8,36864,2] | rois[8,600,4] | anchor[1,36864,4]
// Score GEMM accumulation = splitK2 (bit-matches reference); loc GEMM = plain chain.
// ---------------------------------------------------------------------------

#define NB        8
#define NA        36864
#define HW        4096
#define K_DIM     512
#define N_PRE     12000
#define N_POST    600
#define SORT_N    16384

#define OFF_SCORES 1179648
#define OFF_ROIS   1769472
#define OFF_ANCH   1788672

__device__ float4             g_boxes[NB][NA];
__device__ unsigned           g_su[NB][NA];
__device__ unsigned long long g_cand[NB][SORT_N];
__device__ int                g_C[NB];
__device__ int                g_vcnt[NB];
__device__ float4             g_sboxes[NB][N_PRE];

__constant__ float c_aw[9] = {181.01933598375618f, 362.03867196751236f, 724.0773439350247f,
                              128.0f, 256.0f, 512.0f,
                              90.50966799187809f, 181.01933598375618f, 362.03867196751236f};
__constant__ float c_ah[9] = {90.50966799187809f, 181.01933598375618f, 362.03867196751236f,
                              128.0f, 256.0f, 512.0f,
                              181.01933598375618f, 362.03867196751236f, 724.0773439350247f};

// ---------------------------------------------------------------------------
// K1: fused GEMM (UNCHANGED — bit-exact accumulation orders)
// ---------------------------------------------------------------------------
__global__ __launch_bounds__(128) void gemm_kernel(
    const float* __restrict__ x,
    const float* __restrict__ wsc, const float* __restrict__ bsc,
    const float* __restrict__ wlc, const float* __restrict__ blc,
    float* __restrict__ out)
{
    __shared__ float xs[64 * 128];
    __shared__ float ws[54 * 64];
    const int t   = threadIdx.x;
    const int b   = blockIdx.x;
    const int n   = b >> 5;
    const int hw0 = (b & 31) * 128;
    const float* xb = x + n * (K_DIM * HW) + hw0;

    float acc[36];
    float p0[18], p1[18];
#pragma unroll
    for (int o = 0; o < 36; o++) acc[o] = 0.0f;
#pragma unroll
    for (int o = 0; o < 18; o++) { p0[o] = 0.0f; p1[o] = 0.0f; }

    for (int k0 = 0; k0 < K_DIM; k0 += 64) {
#pragma unroll
        for (int it = 0; it < 16; it++) {
            int v = t + it * 128;
            int r = v >> 5;
            int c = v & 31;
            float4 val = *(const float4*)(xb + (k0 + r) * HW + c * 4);
            *(float4*)&xs[r * 128 + c * 4] = val;
        }
        for (int v = t; v < 864; v += 128) {
            int o = v >> 4;
            int c = v & 15;
            const float* row = (o < 36) ? (wlc + o * K_DIM) : (wsc + (o - 36) * K_DIM);
            *(float4*)&ws[o * 64 + c * 4] = *(const float4*)(row + k0 + c * 4);
        }
        __syncthreads();

        float* sc = (k0 < 256) ? p0 : p1;
        for (int kk = 0; kk < 64; kk += 4) {
            float x0 = xs[(kk + 0) * 128 + t];
            float x1 = xs[(kk + 1) * 128 + t];
            float x2 = xs[(kk + 2) * 128 + t];
            float x3 = xs[(kk + 3) * 128 + t];
#pragma unroll
            for (int o = 0; o < 36; o++) {
                float4 w4 = *(float4*)&ws[o * 64 + kk];
                acc[o] = fmaf(x0, w4.x, acc[o]);
                acc[o] = fmaf(x1, w4.y, acc[o]);
                acc[o] = fmaf(x2, w4.z, acc[o]);
                acc[o] = fmaf(x3, w4.w, acc[o]);
            }
#pragma unroll
            for (int o = 0; o < 18; o++) {
                float4 w4 = *(float4*)&ws[(36 + o) * 64 + kk];
                sc[o] = fmaf(x0, w4.x, sc[o]);
                sc[o] = fmaf(x1, w4.y, sc[o]);
                sc[o] = fmaf(x2, w4.z, sc[o]);
                sc[o] = fmaf(x3, w4.w, sc[o]);
            }
        }
        __syncthreads();
    }

    const int hw = hw0 + t;
    float* lout = out + n * (NA * 4) + hw * 36;
#pragma unroll
    for (int o = 0; o < 36; o++) lout[o] = acc[o] + blc[o];
    float* sout = out + OFF_SCORES + n * (NA * 2) + hw * 18;
#pragma unroll
    for (int o = 0; o < 18; o++) sout[o] = (p0[o] + p1[o]) + bsc[o];
}

// ---------------------------------------------------------------------------
// K2: decode (unchanged)
// ---------------------------------------------------------------------------
__global__ void decode_kernel(float* __restrict__ out)
{
    int g = blockIdx.x * blockDim.x + threadIdx.x;
    if (g >= NB * NA) return;
    int n = g / NA;
    int i = g - n * NA;
    int hw = i / 9;
    int a  = i - hw * 9;

    float sx = (float)((hw & 63) * 16);
    float sy = (float)((hw >> 6) * 16);
    float aw = c_aw[a], ah = c_ah[a];
    float ax1 = sx - 0.5f * aw, ay1 = sy - 0.5f * ah;
    float ax2 = sx + 0.5f * aw, ay2 = sy + 0.5f * ah;

    if (n == 0) {
        *(float4*)(out + OFF_ANCH + i * 4) = make_float4(ax1, ay1, ax2, ay2);
    }

    float aww = ax2 - ax1, ahh = ay2 - ay1;
    float acx = ax1 + 0.5f * aww, acy = ay1 + 0.5f * ahh;

    float4 l = *(const float4*)(out + n * (NA * 4) + i * 4);
    float cx = l.x * aww + acx;
    float cy = l.y * ahh + acy;
    float w  = expf(l.z) * aww;
    float h  = expf(l.w) * ahh;

    float x1 = fminf(fmaxf(cx - 0.5f * w, 0.0f), 1024.0f);
    float y1 = fminf(fmaxf(cy - 0.5f * h, 0.0f), 1024.0f);
    float x2 = fminf(fmaxf(cx + 0.5f * w, 0.0f), 1024.0f);
    float y2 = fminf(fmaxf(cy + 0.5f * h, 0.0f), 1024.0f);

    bool valid = ((x2 - x1) >= 16.0f) && ((y2 - y1) >= 16.0f);

    float2 s = *(const float2*)(out + OFF_SCORES + n * (NA * 2) + i * 2);
    float m  = fmaxf(s.x, s.y);
    float e0 = expf(s.x - m), e1 = expf(s.y - m);
    float fg = e1 / (e0 + e1);

    g_su[n][i]    = valid ? (__float_as_uint(fg) | 0x80000000u) : 0u;
    g_boxes[n][i] = make_float4(x1, y1, x2, y2);
}

// ---------------------------------------------------------------------------
// K3: radix select (unchanged)
// ---------------------------------------------------------------------------
__global__ __launch_bounds__(1024) void select_kernel()
{
    __shared__ unsigned hist[4096];
    __shared__ unsigned psum[256];
    __shared__ int sB1, sAbove, sThr, sCnt;

    const int n = blockIdx.x;
    const int t = threadIdx.x;

    for (int v = t; v < 4096; v += 1024) hist[v] = 0;
    __syncthreads();
    for (int i = t; i < NA; i += 1024) {
        unsigned u = g_su[n][i];
        if (u) atomicAdd(&hist[u >> 20], 1u);
    }
    __syncthreads();
    if (t < 256) {
        unsigned s = 0;
#pragma unroll
        for (int j = 0; j < 16; j++) s += hist[t * 16 + j];
        psum[t] = s;
    }
    __syncthreads();
    if (t == 0) {
        unsigned total = 0;
        for (int c = 0; c < 256; c++) total += psum[c];
        if (total <= N_PRE) {
            sThr = 1;
            sB1  = -1;
            g_vcnt[n] = (int)total;
        } else {
            g_vcnt[n] = N_PRE;
            unsigned acc = 0; int c = 255;
            while (acc + psum[c] < N_PRE) { acc += psum[c]; c--; }
            int bkt = c * 16 + 15;
            while (acc + hist[bkt] < N_PRE) { acc += hist[bkt]; bkt--; }
            sB1 = bkt; sAbove = (int)acc; sThr = 0;
        }
    }
    __syncthreads();
    const int B1 = sB1;
    if (sThr == 0) {
        for (int v = t; v < 4096; v += 1024) hist[v] = 0;
        __syncthreads();
        for (int i = t; i < NA; i += 1024) {
            unsigned u = g_su[n][i];
            if (u && (int)(u >> 20) == B1) atomicAdd(&hist[(u >> 8) & 0xFFFu], 1u);
        }
        __syncthreads();
        if (t < 256) {
            unsigned s = 0;
#pragma unroll
            for (int j = 0; j < 16; j++) s += hist[t * 16 + j];
            psum[t] = s;
        }
        __syncthreads();
        if (t == 0) {
            unsigned K2 = (unsigned)(N_PRE - sAbove);
            unsigned acc = 0; int c = 255;
            while (acc + psum[c] < K2) { acc += psum[c]; c--; }
            int bkt = c * 16 + 15;
            while (acc + hist[bkt] < K2) { acc += hist[bkt]; bkt--; }
            sThr = (B1 << 12) | bkt;
        }
    }
    __syncthreads();
    const unsigned thr = (unsigned)sThr;
    if (t == 0) sCnt = 0;
    __syncthreads();
    for (int i = t; i < NA; i += 1024) {
        unsigned u = g_su[n][i];
        if (u && (u >> 8) >= thr) {
            int p = atomicAdd(&sCnt, 1);
            if (p < SORT_N)
                g_cand[n][p] = (((unsigned long long)u) << 32) | (unsigned)(~i);
        }
    }
    __syncthreads();
    if (t == 0) g_C[n] = min(sCnt, SORT_N);
}

// ---------------------------------------------------------------------------
// K4: bitonic sort with register-local sub-networks (unchanged from round 5)
// ---------------------------------------------------------------------------
#define PH(i) ((i) + ((i) >> 4))
#define SORT_SMEM ((SORT_N + SORT_N / 16) * 8)

__device__ __forceinline__ void cswap_desc(unsigned long long& a, unsigned long long& b, bool desc)
{
    bool sw = desc ? (a < b) : (a > b);
    if (sw) { unsigned long long tmp = a; a = b; b = tmp; }
}

__device__ __forceinline__ void merge16(unsigned long long v[16], bool desc)
{
#pragma unroll
    for (int jj = 8; jj >= 1; jj >>= 1)
#pragma unroll
        for (int idx = 0; idx < 16; idx++)
            if ((idx & jj) == 0) cswap_desc(v[idx], v[idx | jj], desc);
}

__global__ __launch_bounds__(1024) void sort_kernel()
{
    extern __shared__ unsigned long long keys[];
    const int n = blockIdx.x;
    const int t = threadIdx.x;
    const int C = g_C[n];
    const int base = t * 16;

    unsigned long long v[16];
#pragma unroll
    for (int s = 0; s < 16; s++) {
        int i = base + s;
        v[s] = (i < C) ? g_cand[n][i] : 0ull;
    }
#pragma unroll
    for (int kk = 2; kk <= 8; kk <<= 1)
#pragma unroll
        for (int jj = kk >> 1; jj >= 1; jj >>= 1)
#pragma unroll
            for (int idx = 0; idx < 16; idx++)
                if ((idx & jj) == 0) cswap_desc(v[idx], v[idx | jj], (idx & kk) == 0);
    merge16(v, (t & 1) == 0);
#pragma unroll
    for (int s = 0; s < 16; s++) keys[PH(base + s)] = v[s];
    __syncthreads();

    for (int k = 32; k <= SORT_N; k <<= 1) {
        for (int j = k >> 1; j >= 16; j >>= 1) {
#pragma unroll
            for (int p = 0; p < 16; p++) {
                int i = t + p * 1024;
                int l = i ^ j;
                if (l > i) {
                    unsigned long long a = keys[PH(i)], b = keys[PH(l)];
                    bool desc = ((i & k) == 0);
                    if (desc ? (a < b) : (a > b)) { keys[PH(i)] = b; keys[PH(l)] = a; }
                }
            }
            __syncthreads();
        }
#pragma unroll
        for (int s = 0; s < 16; s++) v[s] = keys[PH(base + s)];
        merge16(v, (base & k) == 0);
#pragma unroll
        for (int s = 0; s < 16; s++) keys[PH(base + s)] = v[s];
        __syncthreads();
    }

    for (int p = t; p < N_PRE; p += 1024) {
        unsigned long long kk = keys[PH(p)];
        unsigned idx = ~(unsigned)(kk & 0xFFFFFFFFull);
        float4 b = (kk != 0ull) ? g_boxes[n][idx] : make_float4(0.f, 0.f, 0.f, 0.f);
        g_sboxes[n][p] = b;
    }
}

// ---------------------------------------------------------------------------
// K5: greedy NMS. 1024 threads, STRIDED ownership (thread t owns i = s*1024+t)
// -> conflict-free coalesced smem. SoA float2 layout, areas in registers.
// One barrier per accept (double-buffered per-warp minima).
// ---------------------------------------------------------------------------
#define NMS_T     1024
#define NMS_S     12                       // boxes per thread (12*1024 = 12288 slots)
#define NMS_PAD   (NMS_S * NMS_T)
#define NMS_SMEM  (2 * NMS_PAD * 8)        // s_xx + s_yy (float2 each)

__global__ __launch_bounds__(NMS_T) void nms_kernel(float* __restrict__ out)
{
    extern __shared__ float2 s_mem[];
    float2* s_xx = s_mem;                  // (x1,x2) per box
    float2* s_yy = s_mem + NMS_PAD;        // (y1,y2) per box
    __shared__ int warpmin[2][32];
    __shared__ int s_keep[N_POST];

    const int n = blockIdx.x;
    const int t = threadIdx.x;
    const int wid = t >> 5;
    const int vcnt = g_vcnt[n];

    // stage boxes to SoA smem (coalesced)
    for (int i = t; i < N_PRE; i += NMS_T) {
        float4 b = g_sboxes[n][i];
        s_xx[i] = make_float2(b.x, b.z);
        s_yy[i] = make_float2(b.y, b.w);
    }
    for (int i = N_PRE + t; i < NMS_PAD; i += NMS_T) {
        s_xx[i] = make_float2(0.f, 0.f);
        s_yy[i] = make_float2(0.f, 0.f);
    }
    __syncthreads();

    // per-thread areas (strided ownership), live mask
    float ar[NMS_S];
    unsigned live = 0;
#pragma unroll
    for (int s = 0; s < NMS_S; s++) {
        int i = (s << 10) + t;
        float2 xx = s_xx[i];
        float2 yy = s_yy[i];
        ar[s] = fmaxf(xx.y - xx.x, 0.f) * fmaxf(yy.y - yy.x, 0.f);
        if (i < vcnt) live |= 1u << s;
    }

    // initial per-warp min of live indices (index = s*1024 + t, lexicographic)
    {
        int lm = live ? (((__ffs(live) - 1) << 10) + t) : 0x7FFFFFFF;
        lm = __reduce_min_sync(0xFFFFFFFFu, lm);
        if ((t & 31) == 0) warpmin[0][wid] = lm;
    }
    __syncthreads();

    int kept = 0;
    for (int it = 0; it < N_POST; it++) {
        const int p = it & 1;
        int nxt = warpmin[p][0];
#pragma unroll
        for (int w = 1; w < 32; w++) nxt = min(nxt, warpmin[p][w]);
        if (nxt == 0x7FFFFFFF) break;
        if (t == 0) s_keep[it] = nxt;
        kept = it + 1;

        float2 cxx = s_xx[nxt];            // broadcast (same address all threads)
        float2 cyy = s_yy[nxt];
        float ca = fmaxf(cxx.y - cxx.x, 0.f) * fmaxf(cyy.y - cyy.x, 0.f);
        if ((nxt & 1023) == t) live &= ~(1u << (nxt >> 10));

        if (live) {
            float lo = 0.69f * ca;
#pragma unroll
            for (int s = 0; s < NMS_S; s++) {
                if (live & (1u << s)) {
                    float a1 = ar[s];
                    if (a1 < lo || ca < 0.69f * a1) continue;   // conservative area prune
                    int i = (s << 10) + t;
                    float2 xx = s_xx[i];                         // coalesced, conflict-free
                    float iw = fminf(xx.y, cxx.y) - fmaxf(xx.x, cxx.x);
                    if (iw <= 0.f) continue;
                    float2 yy = s_yy[i];
                    float ih = fminf(yy.y, cyy.y) - fmaxf(yy.x, cyy.x);
                    if (ih <= 0.f) continue;
                    float inter = iw * ih;
                    float iou = inter / (ca + a1 - inter + 1e-9f);  // exact reference form
                    if (iou > 0.7f)
                        live &= ~(1u << s);
                }
            }
        }

        int lm = live ? (((__ffs(live) - 1) << 10) + t) : 0x7FFFFFFF;
        lm = __reduce_min_sync(0xFFFFFFFFu, lm);
        if ((t & 31) == 0) warpmin[p ^ 1][wid] = lm;
        __syncthreads();
    }

    __syncthreads();
    for (int e = t; e < N_POST; e += NMS_T) {
        int ki = (e < kept) ? s_keep[e] : (e - kept);   // pad like the reference
        float2 xx = s_xx[ki];
        float2 yy = s_yy[ki];
        *(float4*)(out + OFF_ROIS + n * (N_POST * 4) + e * 4) =
            make_float4(xx.x, yy.x, xx.y, yy.y);
    }
}

// ---------------------------------------------------------------------------
extern "C" void kernel_launch(void* const* d_in, const int* in_sizes, int n_in,
                              void* d_out, int out_size)
{
    const float* x   = (const float*)d_in[0];
    const float* wsc = (const float*)d_in[1];
    const float* bsc = (const float*)d_in[2];
    const float* wlc = (const float*)d_in[3];
    const float* blc = (const float*)d_in[4];
    float* out = (float*)d_out;

    cudaFuncSetAttribute(sort_kernel, cudaFuncAttributeMaxDynamicSharedMemorySize, SORT_SMEM);
    cudaFuncSetAttribute(nms_kernel,  cudaFuncAttributeMaxDynamicSharedMemorySize, NMS_SMEM);

    gemm_kernel<<<256, 128>>>(x, wsc, bsc, wlc, blc, out);
    decode_kernel<<<(NB * NA + 255) / 256, 256>>>(out);
    select_kernel<<<NB, 1024>>>();
    sort_kernel<<<NB, 1024, SORT_SMEM>>>();
    nms_kernel<<<NB, NMS_T, NMS_SMEM>>>(out);
}

// round 7
// speedup vs baseline: 4.1414x; 3.1899x over previous
#include <cuda_runtime.h>
#include <cuda_bf16.h>
#include <cstdint>

// ---------------------------------------------------------------------------
// RPN: 1x1 conv GEMM -> softmax/decode/clip -> top-12000 select+sort -> greedy NMS
// Outputs: rpn_locs[8,36864,4] | rpn_scores[8,36864,2] | rois[8,600,4] | anchor[1,36864,4]
// Score GEMM accumulation = splitK2 (bit-matches reference); loc GEMM = plain chain.
// NMS: chunked accepted-list algorithm (phase1 vet vs A, compacted pairwise,
// serial bitmap sweep) — exact greedy semantics, no per-accept global iteration.
// ---------------------------------------------------------------------------

#define NB        8
#define NA        36864
#define HW        4096
#define K_DIM     512
#define N_PRE     12000
#define N_POST    600
#define SORT_N    16384

#define OFF_SCORES 1179648
#define OFF_ROIS   1769472
#define OFF_ANCH   1788672

__device__ float4             g_boxes[NB][NA];
__device__ unsigned           g_su[NB][NA];
__device__ unsigned long long g_cand[NB][SORT_N];
__device__ int                g_C[NB];
__device__ int                g_vcnt[NB];
__device__ float4             g_sboxes[NB][N_PRE];

__constant__ float c_aw[9] = {181.01933598375618f, 362.03867196751236f, 724.0773439350247f,
                              128.0f, 256.0f, 512.0f,
                              90.50966799187809f, 181.01933598375618f, 362.03867196751236f};
__constant__ float c_ah[9] = {90.50966799187809f, 181.01933598375618f, 362.03867196751236f,
                              128.0f, 256.0f, 512.0f,
                              181.01933598375618f, 362.03867196751236f, 724.0773439350247f};

// ---------------------------------------------------------------------------
// K1: fused GEMM (UNCHANGED — bit-exact accumulation orders)
// ---------------------------------------------------------------------------
__global__ __launch_bounds__(128) void gemm_kernel(
    const float* __restrict__ x,
    const float* __restrict__ wsc, const float* __restrict__ bsc,
    const float* __restrict__ wlc, const float* __restrict__ blc,
    float* __restrict__ out)
{
    __shared__ float xs[64 * 128];
    __shared__ float ws[54 * 64];
    const int t   = threadIdx.x;
    const int b   = blockIdx.x;
    const int n   = b >> 5;
    const int hw0 = (b & 31) * 128;
    const float* xb = x + n * (K_DIM * HW) + hw0;

    float acc[36];
    float p0[18], p1[18];
#pragma unroll
    for (int o = 0; o < 36; o++) acc[o] = 0.0f;
#pragma unroll
    for (int o = 0; o < 18; o++) { p0[o] = 0.0f; p1[o] = 0.0f; }

    for (int k0 = 0; k0 < K_DIM; k0 += 64) {
#pragma unroll
        for (int it = 0; it < 16; it++) {
            int v = t + it * 128;
            int r = v >> 5;
            int c = v & 31;
            float4 val = *(const float4*)(xb + (k0 + r) * HW + c * 4);
            *(float4*)&xs[r * 128 + c * 4] = val;
        }
        for (int v = t; v < 864; v += 128) {
            int o = v >> 4;
            int c = v & 15;
            const float* row = (o < 36) ? (wlc + o * K_DIM) : (wsc + (o - 36) * K_DIM);
            *(float4*)&ws[o * 64 + c * 4] = *(const float4*)(row + k0 + c * 4);
        }
        __syncthreads();

        float* sc = (k0 < 256) ? p0 : p1;
        for (int kk = 0; kk < 64; kk += 4) {
            float x0 = xs[(kk + 0) * 128 + t];
            float x1 = xs[(kk + 1) * 128 + t];
            float x2 = xs[(kk + 2) * 128 + t];
            float x3 = xs[(kk + 3) * 128 + t];
#pragma unroll
            for (int o = 0; o < 36; o++) {
                float4 w4 = *(float4*)&ws[o * 64 + kk];
                acc[o] = fmaf(x0, w4.x, acc[o]);
                acc[o] = fmaf(x1, w4.y, acc[o]);
                acc[o] = fmaf(x2, w4.z, acc[o]);
                acc[o] = fmaf(x3, w4.w, acc[o]);
            }
#pragma unroll
            for (int o = 0; o < 18; o++) {
                float4 w4 = *(float4*)&ws[(36 + o) * 64 + kk];
                sc[o] = fmaf(x0, w4.x, sc[o]);
                sc[o] = fmaf(x1, w4.y, sc[o]);
                sc[o] = fmaf(x2, w4.z, sc[o]);
                sc[o] = fmaf(x3, w4.w, sc[o]);
            }
        }
        __syncthreads();
    }

    const int hw = hw0 + t;
    float* lout = out + n * (NA * 4) + hw * 36;
#pragma unroll
    for (int o = 0; o < 36; o++) lout[o] = acc[o] + blc[o];
    float* sout = out + OFF_SCORES + n * (NA * 2) + hw * 18;
#pragma unroll
    for (int o = 0; o < 18; o++) sout[o] = (p0[o] + p1[o]) + bsc[o];
}

// ---------------------------------------------------------------------------
// K2: decode (unchanged)
// ---------------------------------------------------------------------------
__global__ void decode_kernel(float* __restrict__ out)
{
    int g = blockIdx.x * blockDim.x + threadIdx.x;
    if (g >= NB * NA) return;
    int n = g / NA;
    int i = g - n * NA;
    int hw = i / 9;
    int a  = i - hw * 9;

    float sx = (float)((hw & 63) * 16);
    float sy = (float)((hw >> 6) * 16);
    float aw = c_aw[a], ah = c_ah[a];
    float ax1 = sx - 0.5f * aw, ay1 = sy - 0.5f * ah;
    float ax2 = sx + 0.5f * aw, ay2 = sy + 0.5f * ah;

    if (n == 0) {
        *(float4*)(out + OFF_ANCH + i * 4) = make_float4(ax1, ay1, ax2, ay2);
    }

    float aww = ax2 - ax1, ahh = ay2 - ay1;
    float acx = ax1 + 0.5f * aww, acy = ay1 + 0.5f * ahh;

    float4 l = *(const float4*)(out + n * (NA * 4) + i * 4);
    float cx = l.x * aww + acx;
    float cy = l.y * ahh + acy;
    float w  = expf(l.z) * aww;
    float h  = expf(l.w) * ahh;

    float x1 = fminf(fmaxf(cx - 0.5f * w, 0.0f), 1024.0f);
    float y1 = fminf(fmaxf(cy - 0.5f * h, 0.0f), 1024.0f);
    float x2 = fminf(fmaxf(cx + 0.5f * w, 0.0f), 1024.0f);
    float y2 = fminf(fmaxf(cy + 0.5f * h, 0.0f), 1024.0f);

    bool valid = ((x2 - x1) >= 16.0f) && ((y2 - y1) >= 16.0f);

    float2 s = *(const float2*)(out + OFF_SCORES + n * (NA * 2) + i * 2);
    float m  = fmaxf(s.x, s.y);
    float e0 = expf(s.x - m), e1 = expf(s.y - m);
    float fg = e1 / (e0 + e1);

    g_su[n][i]    = valid ? (__float_as_uint(fg) | 0x80000000u) : 0u;
    g_boxes[n][i] = make_float4(x1, y1, x2, y2);
}

// ---------------------------------------------------------------------------
// K3: radix select (unchanged)
// ---------------------------------------------------------------------------
__global__ __launch_bounds__(1024) void select_kernel()
{
    __shared__ unsigned hist[4096];
    __shared__ unsigned psum[256];
    __shared__ int sB1, sAbove, sThr, sCnt;

    const int n = blockIdx.x;
    const int t = threadIdx.x;

    for (int v = t; v < 4096; v += 1024) hist[v] = 0;
    __syncthreads();
    for (int i = t; i < NA; i += 1024) {
        unsigned u = g_su[n][i];
        if (u) atomicAdd(&hist[u >> 20], 1u);
    }
    __syncthreads();
    if (t < 256) {
        unsigned s = 0;
#pragma unroll
        for (int j = 0; j < 16; j++) s += hist[t * 16 + j];
        psum[t] = s;
    }
    __syncthreads();
    if (t == 0) {
        unsigned total = 0;
        for (int c = 0; c < 256; c++) total += psum[c];
        if (total <= N_PRE) {
            sThr = 1;
            sB1  = -1;
            g_vcnt[n] = (int)total;
        } else {
            g_vcnt[n] = N_PRE;
            unsigned acc = 0; int c = 255;
            while (acc + psum[c] < N_PRE) { acc += psum[c]; c--; }
            int bkt = c * 16 + 15;
            while (acc + hist[bkt] < N_PRE) { acc += hist[bkt]; bkt--; }
            sB1 = bkt; sAbove = (int)acc; sThr = 0;
        }
    }
    __syncthreads();
    const int B1 = sB1;
    if (sThr == 0) {
        for (int v = t; v < 4096; v += 1024) hist[v] = 0;
        __syncthreads();
        for (int i = t; i < NA; i += 1024) {
            unsigned u = g_su[n][i];
            if (u && (int)(u >> 20) == B1) atomicAdd(&hist[(u >> 8) & 0xFFFu], 1u);
        }
        __syncthreads();
        if (t < 256) {
            unsigned s = 0;
#pragma unroll
            for (int j = 0; j < 16; j++) s += hist[t * 16 + j];
            psum[t] = s;
        }
        __syncthreads();
        if (t == 0) {
            unsigned K2 = (unsigned)(N_PRE - sAbove);
            unsigned acc = 0; int c = 255;
            while (acc + psum[c] < K2) { acc += psum[c]; c--; }
            int bkt = c * 16 + 15;
            while (acc + hist[bkt] < K2) { acc += hist[bkt]; bkt--; }
            sThr = (B1 << 12) | bkt;
        }
    }
    __syncthreads();
    const unsigned thr = (unsigned)sThr;
    if (t == 0) sCnt = 0;
    __syncthreads();
    for (int i = t; i < NA; i += 1024) {
        unsigned u = g_su[n][i];
        if (u && (u >> 8) >= thr) {
            int p = atomicAdd(&sCnt, 1);
            if (p < SORT_N)
                g_cand[n][p] = (((unsigned long long)u) << 32) | (unsigned)(~i);
        }
    }
    __syncthreads();
    if (t == 0) g_C[n] = min(sCnt, SORT_N);
}

// ---------------------------------------------------------------------------
// K4: bitonic sort with register-local sub-networks (unchanged)
// ---------------------------------------------------------------------------
#define PH(i) ((i) + ((i) >> 4))
#define SORT_SMEM ((SORT_N + SORT_N / 16) * 8)

__device__ __forceinline__ void cswap_desc(unsigned long long& a, unsigned long long& b, bool desc)
{
    bool sw = desc ? (a < b) : (a > b);
    if (sw) { unsigned long long tmp = a; a = b; b = tmp; }
}

__device__ __forceinline__ void merge16(unsigned long long v[16], bool desc)
{
#pragma unroll
    for (int jj = 8; jj >= 1; jj >>= 1)
#pragma unroll
        for (int idx = 0; idx < 16; idx++)
            if ((idx & jj) == 0) cswap_desc(v[idx], v[idx | jj], desc);
}

__global__ __launch_bounds__(1024) void sort_kernel()
{
    extern __shared__ unsigned long long keys[];
    const int n = blockIdx.x;
    const int t = threadIdx.x;
    const int C = g_C[n];
    const int base = t * 16;

    unsigned long long v[16];
#pragma unroll
    for (int s = 0; s < 16; s++) {
        int i = base + s;
        v[s] = (i < C) ? g_cand[n][i] : 0ull;
    }
#pragma unroll
    for (int kk = 2; kk <= 8; kk <<= 1)
#pragma unroll
        for (int jj = kk >> 1; jj >= 1; jj >>= 1)
#pragma unroll
            for (int idx = 0; idx < 16; idx++)
                if ((idx & jj) == 0) cswap_desc(v[idx], v[idx | jj], (idx & kk) == 0);
    merge16(v, (t & 1) == 0);
#pragma unroll
    for (int s = 0; s < 16; s++) keys[PH(base + s)] = v[s];
    __syncthreads();

    for (int k = 32; k <= SORT_N; k <<= 1) {
        for (int j = k >> 1; j >= 16; j >>= 1) {
#pragma unroll
            for (int p = 0; p < 16; p++) {
                int i = t + p * 1024;
                int l = i ^ j;
                if (l > i) {
                    unsigned long long a = keys[PH(i)], b = keys[PH(l)];
                    bool desc = ((i & k) == 0);
                    if (desc ? (a < b) : (a > b)) { keys[PH(i)] = b; keys[PH(l)] = a; }
                }
            }
            __syncthreads();
        }
#pragma unroll
        for (int s = 0; s < 16; s++) v[s] = keys[PH(base + s)];
        merge16(v, (base & k) == 0);
#pragma unroll
        for (int s = 0; s < 16; s++) keys[PH(base + s)] = v[s];
        __syncthreads();
    }

    for (int p = t; p < N_PRE; p += 1024) {
        unsigned long long kk = keys[PH(p)];
        unsigned idx = ~(unsigned)(kk & 0xFFFFFFFFull);
        float4 b = (kk != 0ull) ? g_boxes[n][idx] : make_float4(0.f, 0.f, 0.f, 0.f);
        g_sboxes[n][p] = b;
    }
}

// ---------------------------------------------------------------------------
// K5: chunked accepted-list NMS. 1024 threads, chunks of 512 candidates.
// Phase1: vet each candidate vs accepted list (2 threads/cand, early break).
// Compact survivors (stable). Phase2: upper-triangle pairwise IoU bits among
// survivors only. Phase3: warp-0 bitmap sweep resolves intra-chunk order.
// Exact greedy semantics. ~6 barriers per chunk instead of 1 per accept.
// ---------------------------------------------------------------------------
#define NMS_T   1024
#define CHUNK   512

__device__ __forceinline__ bool iou_gt7(float2 xx, float2 yy, float a0,
                                        float2 bx, float2 by, float a1)
{
    float iw = fminf(bx.y, xx.y) - fmaxf(bx.x, xx.x);
    if (iw <= 0.f) return false;
    float ih = fminf(by.y, yy.y) - fmaxf(by.x, yy.x);
    if (ih <= 0.f) return false;
    float inter = iw * ih;
    return inter / (a0 + a1 - inter + 1e-9f) > 0.7f;   // exact reference form
}

__global__ __launch_bounds__(NMS_T) void nms_kernel(float* __restrict__ out)
{
    extern __shared__ char nsm[];
    float2*   cxx    = (float2*)(nsm);                     // [512]
    float2*   cyy    = (float2*)(nsm + 4096);              // [512]
    float2*   axx    = (float2*)(nsm + 8192);              // [600]
    float2*   ayy    = (float2*)(nsm + 12992);             // [600]
    float*    car    = (float*) (nsm + 17792);             // [512]
    float*    aar    = (float*) (nsm + 19840);             // [600]
    unsigned* sup    = (unsigned*)(nsm + 22240);           // [512*16]
    int*      s_keep = (int*)   (nsm + 55008);             // [600]
    int*      list   = (int*)   (nsm + 57408);             // [512]
    int*      s_wcnt = (int*)   (nsm + 59456);             // [16]
    int*      s_woff = (int*)   (nsm + 59520);             // [16]
    int*      s_kept = (int*)   (nsm + 59584);             // [1]
    int*      s_nal  = (int*)   (nsm + 59588);             // [1]
    unsigned char* s_dead = (unsigned char*)(nsm + 59592); // [512]

    const int n = blockIdx.x;
    const int t = threadIdx.x;
    const int vcnt = g_vcnt[n];

    if (t == 0) *s_kept = 0;
    __syncthreads();

    for (int base = 0; base < vcnt; base += CHUNK) {
        const int kept0 = *s_kept;                 // barrier-ordered
        if (kept0 >= N_POST) break;                // uniform
        const int C = min(CHUNK, vcnt - base);

        // load chunk
        if (t < C) {
            float4 b = g_sboxes[n][base + t];
            cxx[t] = make_float2(b.x, b.z);
            cyy[t] = make_float2(b.y, b.w);
            car[t] = fmaxf(b.z - b.x, 0.f) * fmaxf(b.w - b.y, 0.f);
            s_dead[t] = 0;
        }
        __syncthreads();

        // phase 1: vet vs accepted list, 2 threads per candidate (even/odd split)
        {
            const int cand = t & (CHUNK - 1);
            const int half = t >> 9;
            if (cand < C && kept0 > 0) {
                float2 xx = cxx[cand];
                float2 yy = cyy[cand];
                float a0 = car[cand];
                bool dead = false;
                for (int j = half; j < kept0; j += 2) {
                    float a1 = aar[j];
                    if (a1 < 0.69f * a0 || a0 < 0.69f * a1) continue;
                    if (iou_gt7(xx, yy, a0, axx[j], ayy[j], a1)) { dead = true; break; }
                }
                if (dead) s_dead[cand] = 1;
            }
        }
        __syncthreads();

        // stable compaction of survivors (warps 0..15 cover the 512 candidates)
        bool alive = false;
        int  pfx = 0;
        if (t < CHUNK) {
            alive = (t < C) && !s_dead[t];
            unsigned bal = __ballot_sync(0xFFFFFFFFu, alive);
            pfx = __popc(bal & ((1u << (t & 31)) - 1u));
            if ((t & 31) == 0) s_wcnt[t >> 5] = __popc(bal);
        }
        __syncthreads();
        if (t == 0) {
            int acc = 0;
#pragma unroll
            for (int w = 0; w < 16; w++) { s_woff[w] = acc; acc += s_wcnt[w]; }
            *s_nal = acc;
        }
        __syncthreads();
        if (t < CHUNK && alive) list[s_woff[t >> 5] + pfx] = t;
        __syncthreads();

        // phase 2: upper-triangle pairwise IoU among survivors (compacted)
        const int nAlive = *s_nal;
        const int W = (nAlive + 31) >> 5;
        for (int u = t; u < nAlive * W; u += NMS_T) {
            int row = u / W;
            int cw  = u - row * W;
            int i   = list[row];
            float2 xx = cxx[i];
            float2 yy = cyy[i];
            float a0 = car[i];
            unsigned bits = 0;
            int cbase = cw << 5;
            int jmax = min(32, nAlive - cbase);
            for (int j = 0; j < jmax; j++) {
                int cidx = cbase + j;
                if (cidx <= row) continue;                 // only later candidates
                int col = list[cidx];
                float a1 = car[col];
                if (a1 < 0.69f * a0 || a0 < 0.69f * a1) continue;
                if (iou_gt7(xx, yy, a0, cxx[col], cyy[col], a1)) bits |= 1u << j;
            }
            sup[row * 16 + cw] = bits;
        }
        __syncthreads();

        // phase 3: warp-0 bitmap sweep, ascending compacted order
        if (t < 32) {
            int kept = kept0;
            unsigned w16 = 0;
            if (t < W) {
                int rem = nAlive - (t << 5);
                w16 = (rem >= 32) ? 0xFFFFFFFFu : ((1u << rem) - 1u);
            }
            while (kept < N_POST) {
                unsigned nz = __ballot_sync(0xFFFFFFFFu, w16 != 0);
                if (!nz) break;
                int wi = __ffs(nz) - 1;
                unsigned wv = __shfl_sync(0xFFFFFFFFu, w16, wi);
                int bit = __ffs(wv) - 1;
                int r = (wi << 5) + bit;
                int i = list[r];
                if (t == 0) {
                    axx[kept] = cxx[i];
                    ayy[kept] = cyy[i];
                    aar[kept] = car[i];
                    s_keep[kept] = base + i;
                }
                kept++;
                unsigned su_ = (t < W) ? sup[r * 16 + t] : 0u;
                w16 &= ~su_;
                if (t == wi) w16 &= ~(1u << bit);
            }
            if (t == 0) *s_kept = kept;
        }
        __syncthreads();
    }

    const int kept = *s_kept;
    for (int e = t; e < N_POST; e += NMS_T) {
        int ki = (e < kept) ? s_keep[e] : (e - kept);   // pad like the reference
        float4 b = g_sboxes[n][ki];
        *(float4*)(out + OFF_ROIS + n * (N_POST * 4) + e * 4) = b;
    }
}

#define NMS_SMEM 60416

// ---------------------------------------------------------------------------
extern "C" void kernel_launch(void* const* d_in, const int* in_sizes, int n_in,
                              void* d_out, int out_size)
{
    const float* x   = (const float*)d_in[0];
    const float* wsc = (const float*)d_in[1];
    const float* bsc = (const float*)d_in[2];
    const float* wlc = (const float*)d_in[3];
    const float* blc = (const float*)d_in[4];
    float* out = (float*)d_out;

    cudaFuncSetAttribute(sort_kernel, cudaFuncAttributeMaxDynamicSharedMemorySize, SORT_SMEM);
    cudaFuncSetAttribute(nms_kernel,  cudaFuncAttributeMaxDynamicSharedMemorySize, NMS_SMEM);

    gemm_kernel<<<256, 128>>>(x, wsc, bsc, wlc, blc, out);
    decode_kernel<<<(NB * NA + 255) / 256, 256>>>(out);
    select_kernel<<<NB, 1024>>>();
    sort_kernel<<<NB, 1024, SORT_SMEM>>>();
    nms_kernel<<<NB, NMS_T, NMS_SMEM>>>(out);
}

// round 8
// speedup vs baseline: 4.7965x; 1.1582x over previous
#include <cuda_runtime.h>
#include <cuda_bf16.h>
#include <cstdint>

// ---------------------------------------------------------------------------
// RPN: fused GEMM+decode -> top-12000 radix select -> shuffle-bitonic sort -> chunked NMS
// Outputs: rpn_locs[8,36864,4] | rpn_scores[8,36864,2] | rois[8,600,4] | anchor[1,36864,4]
// Score GEMM accumulation = splitK2 (bit-matches reference); loc GEMM = plain chain.
// f32x2 packed FMA: two independent fma.rn per instr -> per-element bit-exact.
// ---------------------------------------------------------------------------

#define NB        8
#define NA        36864
#define HW        4096
#define K_DIM     512
#define N_PRE     12000
#define N_POST    600
#define SORT_N    16384

#define OFF_SCORES 1179648
#define OFF_ROIS   1769472
#define OFF_ANCH   1788672

__device__ float4             g_boxes[NB][NA];
__device__ unsigned           g_su[NB][NA];
__device__ unsigned long long g_cand[NB][SORT_N];
__device__ int                g_C[NB];
__device__ int                g_vcnt[NB];
__device__ float4             g_sboxes[NB][N_PRE];

__constant__ float c_aw[9] = {181.01933598375618f, 362.03867196751236f, 724.0773439350247f,
                              128.0f, 256.0f, 512.0f,
                              90.50966799187809f, 181.01933598375618f, 362.03867196751236f};
__constant__ float c_ah[9] = {90.50966799187809f, 181.01933598375618f, 362.03867196751236f,
                              128.0f, 256.0f, 512.0f,
                              181.01933598375618f, 362.03867196751236f, 724.0773439350247f};

// ---------------------------------------------------------------------------
// packed f32x2 helpers (each half is an independent IEEE fma.rn)
// ---------------------------------------------------------------------------
__device__ __forceinline__ unsigned long long fma2(unsigned long long a,
                                                   unsigned long long b,
                                                   unsigned long long c)
{
    unsigned long long d;
    asm("fma.rn.f32x2 %0, %1, %2, %3;" : "=l"(d) : "l"(a), "l"(b), "l"(c));
    return d;
}
__device__ __forceinline__ unsigned long long packxx(float x)
{
    unsigned long long r;
    unsigned xi = __float_as_uint(x);
    asm("mov.b64 %0, {%1, %2};" : "=l"(r) : "r"(xi), "r"(xi));
    return r;
}
__device__ __forceinline__ float f2lo(unsigned long long u) { return __uint_as_float((unsigned)u); }
__device__ __forceinline__ float f2hi(unsigned long long u) { return __uint_as_float((unsigned)(u >> 32)); }

// inner 64-k block: scp bound to a CONCRETE array at each inline site so
// accumulators stay in registers (no runtime-pointer demotion to local).
__device__ __forceinline__ void gemm_inner(const float* xs,
                                           const unsigned long long* ws2, int t,
                                           unsigned long long (&accp)[18],
                                           unsigned long long (&scp)[9])
{
#pragma unroll 4
    for (int kk = 0; kk < 64; kk++) {
        unsigned long long xp = packxx(xs[kk * 128 + t]);
#pragma unroll
        for (int o2 = 0; o2 < 18; o2++)
            accp[o2] = fma2(ws2[o2 * 64 + kk], xp, accp[o2]);
#pragma unroll
        for (int o2 = 0; o2 < 9; o2++)
            scp[o2] = fma2(ws2[(18 + o2) * 64 + kk], xp, scp[o2]);
    }
}

// ---------------------------------------------------------------------------
// K1: fused GEMM + decode epilogue. 256 blocks (8 n * 32 hw-tiles of 128).
// ---------------------------------------------------------------------------
__global__ __launch_bounds__(128) void gemm_kernel(
    const float* __restrict__ x,
    const float* __restrict__ wsc, const float* __restrict__ bsc,
    const float* __restrict__ wlc, const float* __restrict__ blc,
    float* __restrict__ out)
{
    __shared__ float xs[64 * 128];                    // 32 KB
    __shared__ unsigned long long ws2[27 * 64];       // 13.5 KB, packed (o,o+1) pairs
    const int t   = threadIdx.x;
    const int b   = blockIdx.x;
    const int n   = b >> 5;
    const int hw0 = (b & 31) * 128;
    const float* xb = x + n * (K_DIM * HW) + hw0;

    unsigned long long accp[18], sp0[9], sp1[9];
#pragma unroll
    for (int o = 0; o < 18; o++) accp[o] = 0ull;
#pragma unroll
    for (int o = 0; o < 9; o++) { sp0[o] = 0ull; sp1[o] = 0ull; }

    for (int k0 = 0; k0 < K_DIM; k0 += 64) {
#pragma unroll
        for (int it = 0; it < 16; it++) {
            int v = t + it * 128;
            int r = v >> 5;
            int c = v & 31;
            float4 val = *(const float4*)(xb + (k0 + r) * HW + c * 4);
            *(float4*)&xs[r * 128 + c * 4] = val;
        }
        // stage weights into packed-pair layout: ws2[o2*64+k] = {w[2o2][k], w[2o2+1][k]}
        for (int v = t; v < 864; v += 128) {
            int o = v >> 4;
            int c = v & 15;
            const float* row = (o < 36) ? (wlc + o * K_DIM) : (wsc + (o - 36) * K_DIM);
            float4 w = *(const float4*)(row + k0 + c * 4);
            float* dst = (float*)&ws2[(o >> 1) * 64 + c * 4];
            int half = o & 1;
            dst[0 + half] = w.x;
            dst[2 + half] = w.y;
            dst[4 + half] = w.z;
            dst[6 + half] = w.w;
        }
        __syncthreads();

        if (k0 < 256) gemm_inner(xs, ws2, t, accp, sp0);
        else          gemm_inner(xs, ws2, t, accp, sp1);
        __syncthreads();
    }

    // ---- epilogue: unpack, add bias, write locs/scores, decode boxes inline ----
    const int hw = hw0 + t;
    float lv[36], sv[18];
#pragma unroll
    for (int o2 = 0; o2 < 18; o2++) {
        lv[2 * o2]     = f2lo(accp[o2]) + blc[2 * o2];
        lv[2 * o2 + 1] = f2hi(accp[o2]) + blc[2 * o2 + 1];
    }
#pragma unroll
    for (int o2 = 0; o2 < 9; o2++) {
        sv[2 * o2]     = (f2lo(sp0[o2]) + f2lo(sp1[o2])) + bsc[2 * o2];
        sv[2 * o2 + 1] = (f2hi(sp0[o2]) + f2hi(sp1[o2])) + bsc[2 * o2 + 1];
    }

    float* lout = out + n * (NA * 4) + hw * 36;
#pragma unroll
    for (int o = 0; o < 36; o++) lout[o] = lv[o];
    float* sout = out + OFF_SCORES + n * (NA * 2) + hw * 18;
#pragma unroll
    for (int o = 0; o < 18; o++) sout[o] = sv[o];

    float sx = (float)((hw & 63) * 16);
    float sy = (float)((hw >> 6) * 16);
#pragma unroll
    for (int a = 0; a < 9; a++) {
        int i = hw * 9 + a;
        float aw = c_aw[a], ah = c_ah[a];
        float ax1 = sx - 0.5f * aw, ay1 = sy - 0.5f * ah;
        float ax2 = sx + 0.5f * aw, ay2 = sy + 0.5f * ah;
        if (n == 0)
            *(float4*)(out + OFF_ANCH + i * 4) = make_float4(ax1, ay1, ax2, ay2);

        float aww = ax2 - ax1, ahh = ay2 - ay1;
        float acx = ax1 + 0.5f * aww, acy = ay1 + 0.5f * ahh;

        float cx = lv[a * 4 + 0] * aww + acx;
        float cy = lv[a * 4 + 1] * ahh + acy;
        float w  = expf(lv[a * 4 + 2]) * aww;
        float h  = expf(lv[a * 4 + 3]) * ahh;

        float x1 = fminf(fmaxf(cx - 0.5f * w, 0.0f), 1024.0f);
        float y1 = fminf(fmaxf(cy - 0.5f * h, 0.0f), 1024.0f);
        float x2 = fminf(fmaxf(cx + 0.5f * w, 0.0f), 1024.0f);
        float y2 = fminf(fmaxf(cy + 0.5f * h, 0.0f), 1024.0f);

        bool valid = ((x2 - x1) >= 16.0f) && ((y2 - y1) >= 16.0f);

        float s0 = sv[a * 2], s1 = sv[a * 2 + 1];
        float m  = fmaxf(s0, s1);
        float e0 = expf(s0 - m), e1 = expf(s1 - m);
        float fg = e1 / (e0 + e1);

        g_su[n][i]    = valid ? (__float_as_uint(fg) | 0x80000000u) : 0u;
        g_boxes[n][i] = make_float4(x1, y1, x2, y2);
    }
}

// ---------------------------------------------------------------------------
// K3: radix select (unchanged)
// ---------------------------------------------------------------------------
__global__ __launch_bounds__(1024) void select_kernel()
{
    __shared__ unsigned hist[4096];
    __shared__ unsigned psum[256];
    __shared__ int sB1, sAbove, sThr, sCnt;

    const int n = blockIdx.x;
    const int t = threadIdx.x;

    for (int v = t; v < 4096; v += 1024) hist[v] = 0;
    __syncthreads();
    for (int i = t; i < NA; i += 1024) {
        unsigned u = g_su[n][i];
        if (u) atomicAdd(&hist[u >> 20], 1u);
    }
    __syncthreads();
    if (t < 256) {
        unsigned s = 0;
#pragma unroll
        for (int j = 0; j < 16; j++) s += hist[t * 16 + j];
        psum[t] = s;
    }
    __syncthreads();
    if (t == 0) {
        unsigned total = 0;
        for (int c = 0; c < 256; c++) total += psum[c];
        if (total <= N_PRE) {
            sThr = 1;
            sB1  = -1;
            g_vcnt[n] = (int)total;
        } else {
            g_vcnt[n] = N_PRE;
            unsigned acc = 0; int c = 255;
            while (acc + psum[c] < N_PRE) { acc += psum[c]; c--; }
            int bkt = c * 16 + 15;
            while (acc + hist[bkt] < N_PRE) { acc += hist[bkt]; bkt--; }
            sB1 = bkt; sAbove = (int)acc; sThr = 0;
        }
    }
    __syncthreads();
    const int B1 = sB1;
    if (sThr == 0) {
        for (int v = t; v < 4096; v += 1024) hist[v] = 0;
        __syncthreads();
        for (int i = t; i < NA; i += 1024) {
            unsigned u = g_su[n][i];
            if (u && (int)(u >> 20) == B1) atomicAdd(&hist[(u >> 8) & 0xFFFu], 1u);
        }
        __syncthreads();
        if (t < 256) {
            unsigned s = 0;
#pragma unroll
            for (int j = 0; j < 16; j++) s += hist[t * 16 + j];
            psum[t] = s;
        }
        __syncthreads();
        if (t == 0) {
            unsigned K2 = (unsigned)(N_PRE - sAbove);
            unsigned acc = 0; int c = 255;
            while (acc + psum[c] < K2) { acc += psum[c]; c--; }
            int bkt = c * 16 + 15;
            while (acc + hist[bkt] < K2) { acc += hist[bkt]; bkt--; }
            sThr = (B1 << 12) | bkt;
        }
    }
    __syncthreads();
    const unsigned thr = (unsigned)sThr;
    if (t == 0) sCnt = 0;
    __syncthreads();
    for (int i = t; i < NA; i += 1024) {
        unsigned u = g_su[n][i];
        if (u && (u >> 8) >= thr) {
            int p = atomicAdd(&sCnt, 1);
            if (p < SORT_N)
                g_cand[n][p] = (((unsigned long long)u) << 32) | (unsigned)(~i);
        }
    }
    __syncthreads();
    if (t == 0) g_C[n] = min(sCnt, SORT_N);
}

// ---------------------------------------------------------------------------
// K4: bitonic sort. 16 keys/thread; j<=256 phases via warp shuffles (span 512
// in registers, k=32..512 barrier-free); smem only for j>=512 (15 phases).
// ---------------------------------------------------------------------------
#define PH(i) ((i) + ((i) >> 4))
#define SORT_SMEM ((SORT_N + SORT_N / 16) * 8)

__device__ __forceinline__ void cswap_desc(unsigned long long& a, unsigned long long& b, bool desc)
{
    bool sw = desc ? (a < b) : (a > b);
    if (sw) { unsigned long long tmp = a; a = b; b = tmp; }
}

__device__ __forceinline__ void merge16(unsigned long long v[16], bool desc)
{
#pragma unroll
    for (int jj = 8; jj >= 1; jj >>= 1)
#pragma unroll
        for (int idx = 0; idx < 16; idx++)
            if ((idx & jj) == 0) cswap_desc(v[idx], v[idx | jj], desc);
}

__device__ __forceinline__ void shfl_merge_to16(unsigned long long v[16], int t,
                                                int dmax, bool desc)
{
    for (int d = dmax; d >= 1; d >>= 1) {
        bool up = ((t & d) == 0);
        bool keepmax = (desc == up);
#pragma unroll
        for (int s = 0; s < 16; s++) {
            unsigned long long o = __shfl_xor_sync(0xFFFFFFFFu, v[s], d);
            bool agtb = v[s] > o;
            v[s] = (agtb == keepmax) ? v[s] : o;
        }
    }
    merge16(v, desc);
}

__global__ __launch_bounds__(1024) void sort_kernel()
{
    extern __shared__ unsigned long long keys[];
    const int n = blockIdx.x;
    const int t = threadIdx.x;
    const int C = g_C[n];
    const int base = t * 16;

    unsigned long long v[16];
#pragma unroll
    for (int s = 0; s < 16; s++) {
        int i = base + s;
        v[s] = (i < C) ? g_cand[n][i] : 0ull;
    }
    // local sort to 16 (k=2..8 in-thread, then k=16 merge)
#pragma unroll
    for (int kk = 2; kk <= 8; kk <<= 1)
#pragma unroll
        for (int jj = kk >> 1; jj >= 1; jj >>= 1)
#pragma unroll
            for (int idx = 0; idx < 16; idx++)
                if ((idx & jj) == 0) cswap_desc(v[idx], v[idx | jj], (idx & kk) == 0);
    merge16(v, (t & 1) == 0);

    // k = 32..512 entirely in registers via warp shuffles (no barriers)
    for (int k = 32; k <= 512; k <<= 1)
        shfl_merge_to16(v, t, k >> 5, ((t & (k >> 4)) == 0));

#pragma unroll
    for (int s = 0; s < 16; s++) keys[PH(base + s)] = v[s];
    __syncthreads();

    // k = 1024..16384: smem phases for j>=512, then shuffle+local finish
    for (int k = 1024; k <= SORT_N; k <<= 1) {
        for (int j = k >> 1; j >= 512; j >>= 1) {
#pragma unroll
            for (int p = 0; p < 16; p++) {
                int i = t + p * 1024;
                int l = i ^ j;
                if (l > i) {
                    unsigned long long a = keys[PH(i)], bb = keys[PH(l)];
                    bool desc = ((i & k) == 0);
                    if (desc ? (a < bb) : (a > bb)) { keys[PH(i)] = bb; keys[PH(l)] = a; }
                }
            }
            __syncthreads();
        }
#pragma unroll
        for (int s = 0; s < 16; s++) v[s] = keys[PH(base + s)];
        shfl_merge_to16(v, t, 16, ((t & (k >> 4)) == 0));
#pragma unroll
        for (int s = 0; s < 16; s++) keys[PH(base + s)] = v[s];
        __syncthreads();
    }

    for (int p = t; p < N_PRE; p += 1024) {
        unsigned long long kk = keys[PH(p)];
        unsigned idx = ~(unsigned)(kk & 0xFFFFFFFFull);
        float4 b = (kk != 0ull) ? g_boxes[n][idx] : make_float4(0.f, 0.f, 0.f, 0.f);
        g_sboxes[n][p] = b;
    }
}

// ---------------------------------------------------------------------------
// K5: chunked accepted-list NMS (unchanged from round 7)
// ---------------------------------------------------------------------------
#define NMS_T   1024
#define CHUNK   512

__device__ __forceinline__ bool iou_gt7(float2 xx, float2 yy, float a0,
                                        float2 bx, float2 by, float a1)
{
    float iw = fminf(bx.y, xx.y) - fmaxf(bx.x, xx.x);
    if (iw <= 0.f) return false;
    float ih = fminf(by.y, yy.y) - fmaxf(by.x, yy.x);
    if (ih <= 0.f) return false;
    float inter = iw * ih;
    return inter / (a0 + a1 - inter + 1e-9f) > 0.7f;   // exact reference form
}

__global__ __launch_bounds__(NMS_T) void nms_kernel(float* __restrict__ out)
{
    extern __shared__ char nsm[];
    float2*   cxx    = (float2*)(nsm);
    float2*   cyy    = (float2*)(nsm + 4096);
    float2*   axx    = (float2*)(nsm + 8192);
    float2*   ayy    = (float2*)(nsm + 12992);
    float*    car    = (float*) (nsm + 17792);
    float*    aar    = (float*) (nsm + 19840);
    unsigned* sup    = (unsigned*)(nsm + 22240);
    int*      s_keep = (int*)   (nsm + 55008);
    int*      list   = (int*)   (nsm + 57408);
    int*      s_wcnt = (int*)   (nsm + 59456);
    int*      s_woff = (int*)   (nsm + 59520);
    int*      s_kept = (int*)   (nsm + 59584);
    int*      s_nal  = (int*)   (nsm + 59588);
    unsigned char* s_dead = (unsigned char*)(nsm + 59592);

    const int n = blockIdx.x;
    const int t = threadIdx.x;
    const int vcnt = g_vcnt[n];

    if (t == 0) *s_kept = 0;
    __syncthreads();

    for (int base = 0; base < vcnt; base += CHUNK) {
        const int kept0 = *s_kept;
        if (kept0 >= N_POST) break;
        const int C = min(CHUNK, vcnt - base);

        if (t < C) {
            float4 b = g_sboxes[n][base + t];
            cxx[t] = make_float2(b.x, b.z);
            cyy[t] = make_float2(b.y, b.w);
            car[t] = fmaxf(b.z - b.x, 0.f) * fmaxf(b.w - b.y, 0.f);
            s_dead[t] = 0;
        }
        __syncthreads();

        {
            const int cand = t & (CHUNK - 1);
            const int half = t >> 9;
            if (cand < C && kept0 > 0) {
                float2 xx = cxx[cand];
                float2 yy = cyy[cand];
                float a0 = car[cand];
                bool dead = false;
                for (int j = half; j < kept0; j += 2) {
                    float a1 = aar[j];
                    if (a1 < 0.69f * a0 || a0 < 0.69f * a1) continue;
                    if (iou_gt7(xx, yy, a0, axx[j], ayy[j], a1)) { dead = true; break; }
                }
                if (dead) s_dead[cand] = 1;
            }
        }
        __syncthreads();

        bool alive = false;
        int  pfx = 0;
        if (t < CHUNK) {
            alive = (t < C) && !s_dead[t];
            unsigned bal = __ballot_sync(0xFFFFFFFFu, alive);
            pfx = __popc(bal & ((1u << (t & 31)) - 1u));
            if ((t & 31) == 0) s_wcnt[t >> 5] = __popc(bal);
        }
        __syncthreads();
        if (t == 0) {
            int acc = 0;
#pragma unroll
            for (int w = 0; w < 16; w++) { s_woff[w] = acc; acc += s_wcnt[w]; }
            *s_nal = acc;
        }
        __syncthreads();
        if (t < CHUNK && alive) list[s_woff[t >> 5] + pfx] = t;
        __syncthreads();

        const int nAlive = *s_nal;
        const int W = (nAlive + 31) >> 5;
        for (int u = t; u < nAlive * W; u += NMS_T) {
            int row = u / W;
            int cw  = u - row * W;
            int i   = list[row];
            float2 xx = cxx[i];
            float2 yy = cyy[i];
            float a0 = car[i];
            unsigned bits = 0;
            int cbase = cw << 5;
            int jmax = min(32, nAlive - cbase);
            for (int j = 0; j < jmax; j++) {
                int cidx = cbase + j;
                if (cidx <= row) continue;
                int col = list[cidx];
                float a1 = car[col];
                if (a1 < 0.69f * a0 || a0 < 0.69f * a1) continue;
                if (iou_gt7(xx, yy, a0, cxx[col], cyy[col], a1)) bits |= 1u << j;
            }
            sup[row * 16 + cw] = bits;
        }
        __syncthreads();

        if (t < 32) {
            int kept = kept0;
            unsigned w16 = 0;
            if (t < W) {
                int rem = nAlive - (t << 5);
                w16 = (rem >= 32) ? 0xFFFFFFFFu : ((1u << rem) - 1u);
            }
            while (kept < N_POST) {
                unsigned nz = __ballot_sync(0xFFFFFFFFu, w16 != 0);
                if (!nz) break;
                int wi = __ffs(nz) - 1;
                unsigned wv = __shfl_sync(0xFFFFFFFFu, w16, wi);
                int bit = __ffs(wv) - 1;
                int r = (wi << 5) + bit;
                int i = list[r];
                if (t == 0) {
                    axx[kept] = cxx[i];
                    ayy[kept] = cyy[i];
                    aar[kept] = car[i];
                    s_keep[kept] = base + i;
                }
                kept++;
                unsigned su_ = (t < W) ? sup[r * 16 + t] : 0u;
                w16 &= ~su_;
                if (t == wi) w16 &= ~(1u << bit);
            }
            if (t == 0) *s_kept = kept;
        }
        __syncthreads();
    }

    const int kept = *s_kept;
    for (int e = t; e < N_POST; e += NMS_T) {
        int ki = (e < kept) ? s_keep[e] : (e - kept);
        float4 b = g_sboxes[n][ki];
        *(float4*)(out + OFF_ROIS + n * (N_POST * 4) + e * 4) = b;
    }
}

#define NMS_SMEM 60416

// ---------------------------------------------------------------------------
extern "C" void kernel_launch(void* const* d_in, const int* in_sizes, int n_in,
                              void* d_out, int out_size)
{
    const float* x   = (const float*)d_in[0];
    const float* wsc = (const float*)d_in[1];
    const float* bsc = (const float*)d_in[2];
    const float* wlc = (const float*)d_in[3];
    const float* blc = (const float*)d_in[4];
    float* out = (float*)d_out;

    cudaFuncSetAttribute(sort_kernel, cudaFuncAttributeMaxDynamicSharedMemorySize, SORT_SMEM);
    cudaFuncSetAttribute(nms_kernel,  cudaFuncAttributeMaxDynamicSharedMemorySize, NMS_SMEM);

    gemm_kernel<<<256, 128>>>(x, wsc, bsc, wlc, blc, out);
    select_kernel<<<NB, 1024>>>();
    sort_kernel<<<NB, 1024, SORT_SMEM>>>();
    nms_kernel<<<NB, NMS_T, NMS_SMEM>>>(out);
}

// round 9
// speedup vs baseline: 4.9207x; 1.0259x over previous
#include <cuda_runtime.h>
#include <cuda_bf16.h>
#include <cstdint>

// ---------------------------------------------------------------------------
// RPN: fused GEMM+decode -> top-12000 radix select -> shuffle-bitonic sort -> chunked NMS
// Outputs: rpn_locs[8,36864,4] | rpn_scores[8,36864,2] | rois[8,600,4] | anchor[1,36864,4]
// Score GEMM accumulation = splitK2 (bit-matches reference); loc GEMM = plain chain.
// f32x2 packed FMA: two independent fma.rn per instr -> per-element bit-exact.
// ---------------------------------------------------------------------------

#define NB        8
#define NA        36864
#define HW        4096
#define K_DIM     512
#define N_PRE     12000
#define N_POST    600
#define SORT_N    16384

#define OFF_SCORES 1179648
#define OFF_ROIS   1769472
#define OFF_ANCH   1788672

__device__ float4             g_boxes[NB][NA];
__device__ unsigned           g_su[NB][NA];
__device__ unsigned long long g_cand[NB][SORT_N];
__device__ int                g_C[NB];
__device__ int                g_vcnt[NB];
__device__ float4             g_sboxes[NB][N_PRE];

__constant__ float c_aw[9] = {181.01933598375618f, 362.03867196751236f, 724.0773439350247f,
                              128.0f, 256.0f, 512.0f,
                              90.50966799187809f, 181.01933598375618f, 362.03867196751236f};
__constant__ float c_ah[9] = {90.50966799187809f, 181.01933598375618f, 362.03867196751236f,
                              128.0f, 256.0f, 512.0f,
                              181.01933598375618f, 362.03867196751236f, 724.0773439350247f};

// ---------------------------------------------------------------------------
// packed f32x2 helpers
// ---------------------------------------------------------------------------
__device__ __forceinline__ unsigned long long fma2(unsigned long long a,
                                                   unsigned long long b,
                                                   unsigned long long c)
{
    unsigned long long d;
    asm("fma.rn.f32x2 %0, %1, %2, %3;" : "=l"(d) : "l"(a), "l"(b), "l"(c));
    return d;
}
__device__ __forceinline__ unsigned long long packxx(float x)
{
    unsigned long long r;
    unsigned xi = __float_as_uint(x);
    asm("mov.b64 %0, {%1, %2};" : "=l"(r) : "r"(xi), "r"(xi));
    return r;
}
__device__ __forceinline__ float f2lo(unsigned long long u) { return __uint_as_float((unsigned)u); }
__device__ __forceinline__ float f2hi(unsigned long long u) { return __uint_as_float((unsigned)(u >> 32)); }

__device__ __forceinline__ void gemm_inner(const float* xs,
                                           const unsigned long long* ws2, int t,
                                           unsigned long long (&accp)[18],
                                           unsigned long long (&scp)[9])
{
#pragma unroll 4
    for (int kk = 0; kk < 64; kk++) {
        unsigned long long xp = packxx(xs[kk * 128 + t]);
#pragma unroll
        for (int o2 = 0; o2 < 18; o2++)
            accp[o2] = fma2(ws2[o2 * 64 + kk], xp, accp[o2]);
#pragma unroll
        for (int o2 = 0; o2 < 9; o2++)
            scp[o2] = fma2(ws2[(18 + o2) * 64 + kk], xp, scp[o2]);
    }
}

// ---------------------------------------------------------------------------
// K1: fused GEMM + decode epilogue (unchanged from round 8)
// ---------------------------------------------------------------------------
__global__ __launch_bounds__(128) void gemm_kernel(
    const float* __restrict__ x,
    const float* __restrict__ wsc, const float* __restrict__ bsc,
    const float* __restrict__ wlc, const float* __restrict__ blc,
    float* __restrict__ out)
{
    __shared__ float xs[64 * 128];
    __shared__ unsigned long long ws2[27 * 64];
    const int t   = threadIdx.x;
    const int b   = blockIdx.x;
    const int n   = b >> 5;
    const int hw0 = (b & 31) * 128;
    const float* xb = x + n * (K_DIM * HW) + hw0;

    unsigned long long accp[18], sp0[9], sp1[9];
#pragma unroll
    for (int o = 0; o < 18; o++) accp[o] = 0ull;
#pragma unroll
    for (int o = 0; o < 9; o++) { sp0[o] = 0ull; sp1[o] = 0ull; }

    for (int k0 = 0; k0 < K_DIM; k0 += 64) {
#pragma unroll
        for (int it = 0; it < 16; it++) {
            int v = t + it * 128;
            int r = v >> 5;
            int c = v & 31;
            float4 val = *(const float4*)(xb + (k0 + r) * HW + c * 4);
            *(float4*)&xs[r * 128 + c * 4] = val;
        }
        for (int v = t; v < 864; v += 128) {
            int o = v >> 4;
            int c = v & 15;
            const float* row = (o < 36) ? (wlc + o * K_DIM) : (wsc + (o - 36) * K_DIM);
            float4 w = *(const float4*)(row + k0 + c * 4);
            float* dst = (float*)&ws2[(o >> 1) * 64 + c * 4];
            int half = o & 1;
            dst[0 + half] = w.x;
            dst[2 + half] = w.y;
            dst[4 + half] = w.z;
            dst[6 + half] = w.w;
        }
        __syncthreads();

        if (k0 < 256) gemm_inner(xs, ws2, t, accp, sp0);
        else          gemm_inner(xs, ws2, t, accp, sp1);
        __syncthreads();
    }

    const int hw = hw0 + t;
    float lv[36], sv[18];
#pragma unroll
    for (int o2 = 0; o2 < 18; o2++) {
        lv[2 * o2]     = f2lo(accp[o2]) + blc[2 * o2];
        lv[2 * o2 + 1] = f2hi(accp[o2]) + blc[2 * o2 + 1];
    }
#pragma unroll
    for (int o2 = 0; o2 < 9; o2++) {
        sv[2 * o2]     = (f2lo(sp0[o2]) + f2lo(sp1[o2])) + bsc[2 * o2];
        sv[2 * o2 + 1] = (f2hi(sp0[o2]) + f2hi(sp1[o2])) + bsc[2 * o2 + 1];
    }

    float* lout = out + n * (NA * 4) + hw * 36;
#pragma unroll
    for (int o = 0; o < 36; o++) lout[o] = lv[o];
    float* sout = out + OFF_SCORES + n * (NA * 2) + hw * 18;
#pragma unroll
    for (int o = 0; o < 18; o++) sout[o] = sv[o];

    float sx = (float)((hw & 63) * 16);
    float sy = (float)((hw >> 6) * 16);
#pragma unroll
    for (int a = 0; a < 9; a++) {
        int i = hw * 9 + a;
        float aw = c_aw[a], ah = c_ah[a];
        float ax1 = sx - 0.5f * aw, ay1 = sy - 0.5f * ah;
        float ax2 = sx + 0.5f * aw, ay2 = sy + 0.5f * ah;
        if (n == 0)
            *(float4*)(out + OFF_ANCH + i * 4) = make_float4(ax1, ay1, ax2, ay2);

        float aww = ax2 - ax1, ahh = ay2 - ay1;
        float acx = ax1 + 0.5f * aww, acy = ay1 + 0.5f * ahh;

        float cx = lv[a * 4 + 0] * aww + acx;
        float cy = lv[a * 4 + 1] * ahh + acy;
        float w  = expf(lv[a * 4 + 2]) * aww;
        float h  = expf(lv[a * 4 + 3]) * ahh;

        float x1 = fminf(fmaxf(cx - 0.5f * w, 0.0f), 1024.0f);
        float y1 = fminf(fmaxf(cy - 0.5f * h, 0.0f), 1024.0f);
        float x2 = fminf(fmaxf(cx + 0.5f * w, 0.0f), 1024.0f);
        float y2 = fminf(fmaxf(cy + 0.5f * h, 0.0f), 1024.0f);

        bool valid = ((x2 - x1) >= 16.0f) && ((y2 - y1) >= 16.0f);

        float s0 = sv[a * 2], s1 = sv[a * 2 + 1];
        float m  = fmaxf(s0, s1);
        float e0 = expf(s0 - m), e1 = expf(s1 - m);
        float fg = e1 / (e0 + e1);

        g_su[n][i]    = valid ? (__float_as_uint(fg) | 0x80000000u) : 0u;
        g_boxes[n][i] = make_float4(x1, y1, x2, y2);
    }
}

// ---------------------------------------------------------------------------
// K3: radix select (unchanged)
// ---------------------------------------------------------------------------
__global__ __launch_bounds__(1024) void select_kernel()
{
    __shared__ unsigned hist[4096];
    __shared__ unsigned psum[256];
    __shared__ int sB1, sAbove, sThr, sCnt;

    const int n = blockIdx.x;
    const int t = threadIdx.x;

    for (int v = t; v < 4096; v += 1024) hist[v] = 0;
    __syncthreads();
    for (int i = t; i < NA; i += 1024) {
        unsigned u = g_su[n][i];
        if (u) atomicAdd(&hist[u >> 20], 1u);
    }
    __syncthreads();
    if (t < 256) {
        unsigned s = 0;
#pragma unroll
        for (int j = 0; j < 16; j++) s += hist[t * 16 + j];
        psum[t] = s;
    }
    __syncthreads();
    if (t == 0) {
        unsigned total = 0;
        for (int c = 0; c < 256; c++) total += psum[c];
        if (total <= N_PRE) {
            sThr = 1;
            sB1  = -1;
            g_vcnt[n] = (int)total;
        } else {
            g_vcnt[n] = N_PRE;
            unsigned acc = 0; int c = 255;
            while (acc + psum[c] < N_PRE) { acc += psum[c]; c--; }
            int bkt = c * 16 + 15;
            while (acc + hist[bkt] < N_PRE) { acc += hist[bkt]; bkt--; }
            sB1 = bkt; sAbove = (int)acc; sThr = 0;
        }
    }
    __syncthreads();
    const int B1 = sB1;
    if (sThr == 0) {
        for (int v = t; v < 4096; v += 1024) hist[v] = 0;
        __syncthreads();
        for (int i = t; i < NA; i += 1024) {
            unsigned u = g_su[n][i];
            if (u && (int)(u >> 20) == B1) atomicAdd(&hist[(u >> 8) & 0xFFFu], 1u);
        }
        __syncthreads();
        if (t < 256) {
            unsigned s = 0;
#pragma unroll
            for (int j = 0; j < 16; j++) s += hist[t * 16 + j];
            psum[t] = s;
        }
        __syncthreads();
        if (t == 0) {
            unsigned K2 = (unsigned)(N_PRE - sAbove);
            unsigned acc = 0; int c = 255;
            while (acc + psum[c] < K2) { acc += psum[c]; c--; }
            int bkt = c * 16 + 15;
            while (acc + hist[bkt] < K2) { acc += hist[bkt]; bkt--; }
            sThr = (B1 << 12) | bkt;
        }
    }
    __syncthreads();
    const unsigned thr = (unsigned)sThr;
    if (t == 0) sCnt = 0;
    __syncthreads();
    for (int i = t; i < NA; i += 1024) {
        unsigned u = g_su[n][i];
        if (u && (u >> 8) >= thr) {
            int p = atomicAdd(&sCnt, 1);
            if (p < SORT_N)
                g_cand[n][p] = (((unsigned long long)u) << 32) | (unsigned)(~i);
        }
    }
    __syncthreads();
    if (t == 0) g_C[n] = min(sCnt, SORT_N);
}

// ---------------------------------------------------------------------------
// K4: shuffle-bitonic sort (unchanged from round 8)
// ---------------------------------------------------------------------------
#define PH(i) ((i) + ((i) >> 4))
#define SORT_SMEM ((SORT_N + SORT_N / 16) * 8)

__device__ __forceinline__ void cswap_desc(unsigned long long& a, unsigned long long& b, bool desc)
{
    bool sw = desc ? (a < b) : (a > b);
    if (sw) { unsigned long long tmp = a; a = b; b = tmp; }
}

__device__ __forceinline__ void merge16(unsigned long long v[16], bool desc)
{
#pragma unroll
    for (int jj = 8; jj >= 1; jj >>= 1)
#pragma unroll
        for (int idx = 0; idx < 16; idx++)
            if ((idx & jj) == 0) cswap_desc(v[idx], v[idx | jj], desc);
}

__device__ __forceinline__ void shfl_merge_to16(unsigned long long v[16], int t,
                                                int dmax, bool desc)
{
    for (int d = dmax; d >= 1; d >>= 1) {
        bool up = ((t & d) == 0);
        bool keepmax = (desc == up);
#pragma unroll
        for (int s = 0; s < 16; s++) {
            unsigned long long o = __shfl_xor_sync(0xFFFFFFFFu, v[s], d);
            bool agtb = v[s] > o;
            v[s] = (agtb == keepmax) ? v[s] : o;
        }
    }
    merge16(v, desc);
}

__global__ __launch_bounds__(1024) void sort_kernel()
{
    extern __shared__ unsigned long long keys[];
    const int n = blockIdx.x;
    const int t = threadIdx.x;
    const int C = g_C[n];
    const int base = t * 16;

    unsigned long long v[16];
#pragma unroll
    for (int s = 0; s < 16; s++) {
        int i = base + s;
        v[s] = (i < C) ? g_cand[n][i] : 0ull;
    }
#pragma unroll
    for (int kk = 2; kk <= 8; kk <<= 1)
#pragma unroll
        for (int jj = kk >> 1; jj >= 1; jj >>= 1)
#pragma unroll
            for (int idx = 0; idx < 16; idx++)
                if ((idx & jj) == 0) cswap_desc(v[idx], v[idx | jj], (idx & kk) == 0);
    merge16(v, (t & 1) == 0);

    for (int k = 32; k <= 512; k <<= 1)
        shfl_merge_to16(v, t, k >> 5, ((t & (k >> 4)) == 0));

#pragma unroll
    for (int s = 0; s < 16; s++) keys[PH(base + s)] = v[s];
    __syncthreads();

    for (int k = 1024; k <= SORT_N; k <<= 1) {
        for (int j = k >> 1; j >= 512; j >>= 1) {
#pragma unroll
            for (int p = 0; p < 16; p++) {
                int i = t + p * 1024;
                int l = i ^ j;
                if (l > i) {
                    unsigned long long a = keys[PH(i)], bb = keys[PH(l)];
                    bool desc = ((i & k) == 0);
                    if (desc ? (a < bb) : (a > bb)) { keys[PH(i)] = bb; keys[PH(l)] = a; }
                }
            }
            __syncthreads();
        }
#pragma unroll
        for (int s = 0; s < 16; s++) v[s] = keys[PH(base + s)];
        shfl_merge_to16(v, t, 16, ((t & (k >> 4)) == 0));
#pragma unroll
        for (int s = 0; s < 16; s++) keys[PH(base + s)] = v[s];
        __syncthreads();
    }

    for (int p = t; p < N_PRE; p += 1024) {
        unsigned long long kk = keys[PH(p)];
        unsigned idx = ~(unsigned)(kk & 0xFFFFFFFFull);
        float4 b = (kk != 0ull) ? g_boxes[n][idx] : make_float4(0.f, 0.f, 0.f, 0.f);
        g_sboxes[n][p] = b;
    }
}

// ---------------------------------------------------------------------------
// K5: chunked accepted-list NMS.
// Phase 1 pipelined: accepted boxes as float4 (1×LDS.128/check, area recomputed
// bit-identically), unroll x4 with group-granularity early exit.
// ---------------------------------------------------------------------------
#define NMS_T   1024
#define CHUNK   512

__device__ __forceinline__ bool iou_gt7(float2 xx, float2 yy, float a0,
                                        float2 bx, float2 by, float a1)
{
    float iw = fminf(bx.y, xx.y) - fmaxf(bx.x, xx.x);
    if (iw <= 0.f) return false;
    float ih = fminf(by.y, yy.y) - fmaxf(by.x, yy.x);
    if (ih <= 0.f) return false;
    float inter = iw * ih;
    return inter / (a0 + a1 - inter + 1e-9f) > 0.7f;   // exact reference form
}

__global__ __launch_bounds__(NMS_T) void nms_kernel(float* __restrict__ out)
{
    extern __shared__ char nsm[];
    float2*   cxx    = (float2*)(nsm);                     // [512]
    float2*   cyy    = (float2*)(nsm + 4096);              // [512]
    float4*   abox   = (float4*)(nsm + 8192);              // [600] accepted (x1,y1,x2,y2)
    float*    car    = (float*) (nsm + 17792);             // [512]
    unsigned* sup    = (unsigned*)(nsm + 19840);           // [512*16]
    int*      s_keep = (int*)   (nsm + 52608);             // [600]
    int*      list   = (int*)   (nsm + 55008);             // [512]
    int*      s_wcnt = (int*)   (nsm + 57056);             // [16]
    int*      s_woff = (int*)   (nsm + 57120);             // [16]
    int*      s_kept = (int*)   (nsm + 57184);             // [1]
    int*      s_nal  = (int*)   (nsm + 57188);             // [1]
    unsigned char* s_dead = (unsigned char*)(nsm + 57192); // [512]

    const int n = blockIdx.x;
    const int t = threadIdx.x;
    const int vcnt = g_vcnt[n];

    if (t == 0) *s_kept = 0;
    __syncthreads();

    for (int base = 0; base < vcnt; base += CHUNK) {
        const int kept0 = *s_kept;
        if (kept0 >= N_POST) break;
        const int C = min(CHUNK, vcnt - base);

        if (t < C) {
            float4 b = g_sboxes[n][base + t];
            cxx[t] = make_float2(b.x, b.z);
            cyy[t] = make_float2(b.y, b.w);
            car[t] = fmaxf(b.z - b.x, 0.f) * fmaxf(b.w - b.y, 0.f);
            s_dead[t] = 0;
        }
        __syncthreads();

        // phase 1: vet vs accepted list. 2 threads/cand, 4-wide pipelined groups.
        {
            const int cand = t & (CHUNK - 1);
            const int half = t >> 9;
            if (cand < C && kept0 > 0) {
                float2 xx = cxx[cand];
                float2 yy = cyy[cand];
                float a0 = car[cand];
                float lo = 0.69f * a0;
                bool dead = false;
                for (int j0 = half * 4; j0 < kept0 && !dead; j0 += 8) {
#pragma unroll
                    for (int u = 0; u < 4; u++) {
                        int j = j0 + u;
                        if (j < kept0) {
                            float4 ab = abox[j];                       // LDS.128, 4 in flight
                            float a1 = (ab.z - ab.x) * (ab.w - ab.y);  // == stored area bitwise
                            if (a1 < lo || a0 < 0.69f * a1) continue;
                            float iw = fminf(ab.z, xx.y) - fmaxf(ab.x, xx.x);
                            if (iw <= 0.f) continue;
                            float ih = fminf(ab.w, yy.y) - fmaxf(ab.y, yy.x);
                            if (ih <= 0.f) continue;
                            float inter = iw * ih;
                            if (inter / (a0 + a1 - inter + 1e-9f) > 0.7f) dead = true;
                        }
                    }
                }
                if (dead) s_dead[cand] = 1;
            }
        }
        __syncthreads();

        // stable compaction of survivors
        bool alive = false;
        int  pfx = 0;
        if (t < CHUNK) {
            alive = (t < C) && !s_dead[t];
            unsigned bal = __ballot_sync(0xFFFFFFFFu, alive);
            pfx = __popc(bal & ((1u << (t & 31)) - 1u));
            if ((t & 31) == 0) s_wcnt[t >> 5] = __popc(bal);
        }
        __syncthreads();
        if (t == 0) {
            int acc = 0;
#pragma unroll
            for (int w = 0; w < 16; w++) { s_woff[w] = acc; acc += s_wcnt[w]; }
            *s_nal = acc;
        }
        __syncthreads();
        if (t < CHUNK && alive) list[s_woff[t >> 5] + pfx] = t;
        __syncthreads();

        // phase 2: upper-triangle pairwise IoU among survivors
        const int nAlive = *s_nal;
        const int W = (nAlive + 31) >> 5;
        for (int u = t; u < nAlive * W; u += NMS_T) {
            int row = u / W;
            int cw  = u - row * W;
            int i   = list[row];
            float2 xx = cxx[i];
            float2 yy = cyy[i];
            float a0 = car[i];
            unsigned bits = 0;
            int cbase = cw << 5;
            int jmax = min(32, nAlive - cbase);
            for (int j = 0; j < jmax; j++) {
                int cidx = cbase + j;
                if (cidx <= row) continue;
                int col = list[cidx];
                float a1 = car[col];
                if (a1 < 0.69f * a0 || a0 < 0.69f * a1) continue;
                if (iou_gt7(xx, yy, a0, cxx[col], cyy[col], a1)) bits |= 1u << j;
            }
            sup[row * 16 + cw] = bits;
        }
        __syncthreads();

        // phase 3: warp-0 bitmap sweep
        if (t < 32) {
            int kept = kept0;
            unsigned w16 = 0;
            if (t < W) {
                int rem = nAlive - (t << 5);
                w16 = (rem >= 32) ? 0xFFFFFFFFu : ((1u << rem) - 1u);
            }
            while (kept < N_POST) {
                unsigned nz = __ballot_sync(0xFFFFFFFFu, w16 != 0);
                if (!nz) break;
                int wi = __ffs(nz) - 1;
                unsigned wv = __shfl_sync(0xFFFFFFFFu, w16, wi);
                int bit = __ffs(wv) - 1;
                int r = (wi << 5) + bit;
                int i = list[r];
                if (t == 0) {
                    float2 xx = cxx[i];
                    float2 yy = cyy[i];
                    abox[kept] = make_float4(xx.x, yy.x, xx.y, yy.y);
                    s_keep[kept] = base + i;
                }
                kept++;
                unsigned su_ = (t < W) ? sup[r * 16 + t] : 0u;
                w16 &= ~su_;
                if (t == wi) w16 &= ~(1u << bit);
            }
            if (t == 0) *s_kept = kept;
        }
        __syncthreads();
    }

    const int kept = *s_kept;
    for (int e = t; e < N_POST; e += NMS_T) {
        int ki = (e < kept) ? s_keep[e] : (e - kept);
        float4 b = g_sboxes[n][ki];
        *(float4*)(out + OFF_ROIS + n * (N_POST * 4) + e * 4) = b;
    }
}

#define NMS_SMEM 57856

// ---------------------------------------------------------------------------
extern "C" void kernel_launch(void* const* d_in, const int* in_sizes, int n_in,
                              void* d_out, int out_size)
{
    const float* x   = (const float*)d_in[0];
    const float* wsc = (const float*)d_in[1];
    const float* bsc = (const float*)d_in[2];
    const float* wlc = (const float*)d_in[3];
    const float* blc = (const float*)d_in[4];
    float* out = (float*)d_out;

    cudaFuncSetAttribute(sort_kernel, cudaFuncAttributeMaxDynamicSharedMemorySize, SORT_SMEM);
    cudaFuncSetAttribute(nms_kernel,  cudaFuncAttributeMaxDynamicSharedMemorySize, NMS_SMEM);

    gemm_kernel<<<256, 128>>>(x, wsc, bsc, wlc, blc, out);
    select_kernel<<<NB, 1024>>>();
    sort_kernel<<<NB, 1024, SORT_SMEM>>>();
    nms_kernel<<<NB, NMS_T, NMS_SMEM>>>(out);
}